// round 13
// baseline (speedup 1.0000x reference)
#include <cuda_runtime.h>
#include <cuda_fp16.h>
#include <math.h>
#include <stdint.h>

// ---------------------------------------------------------------------------
// B=16, S=2048, C=8, P=16 -> N=128 patches, T=2048 tokens
// PD=128, IRH=512, D=512, NH=8, dh=64, L=12, E=4, H=2048, top-2 routing
// Split-precision fp16 HMMA GEMMs with PRE-SPLIT hi/lo operands in global
// memory (weights split+transposed once per launch; activations split at
// producer epilogues). GEMM inner loop: cp.async 3-stage + ldmatrix + mma.
// ---------------------------------------------------------------------------
#define T_TOK 2048
#define DIM   512
#define HDIM  2048

__device__ float g_patches[T_TOK * 128];
__device__ float g_tmp    [T_TOK * 512];
__device__ float g_hp     [T_TOK * 128];
__device__ float g_h      [T_TOK * DIM];
__device__ float g_hn     [T_TOK * DIM];
__device__ float g_qkv    [T_TOK * 3 * DIM];
__device__ int   g_cnt    [4];
__device__ int   g_idx    [4 * T_TOK];
__device__ float g_rw     [4 * T_TOK];

// pre-split halves: weights (transposed [N][K]) + activations
__device__ __half g_qkvTh[12 * 1536 * 512];
__device__ __half g_qkvTl[12 * 1536 * 512];
__device__ __half g_outTh[12 * 512 * 512];
__device__ __half g_outTl[12 * 512 * 512];
__device__ __half g_e1Th [48 * 2048 * 512];
__device__ __half g_e1Tl [48 * 2048 * 512];
__device__ __half g_e2Th [48 * 512 * 2048];
__device__ __half g_e2Tl [48 * 512 * 2048];
__device__ __half g_hnh  [T_TOK * 512];
__device__ __half g_hnl  [T_TOK * 512];
__device__ __half g_ath  [T_TOK * 512];
__device__ __half g_atl  [T_TOK * 512];
__device__ __half g_ehh  [4 * T_TOK * 2048];
__device__ __half g_ehl  [4 * T_TOK * 2048];

// ---- helpers ---------------------------------------------------------------
__device__ __forceinline__ void split2(float f0, float f1, uint32_t& hi, uint32_t& lo) {
    __half2 h = __floats2half2_rn(f0, f1);
    float2 hf = __half22float2(h);
    __half2 l = __floats2half2_rn(f0 - hf.x, f1 - hf.y);
    hi = *(uint32_t*)&h;
    lo = *(uint32_t*)&l;
}
__device__ __forceinline__ void mma_f16(float* d, const uint32_t* a, const uint32_t* b) {
    asm volatile(
        "mma.sync.aligned.m16n8k16.row.col.f32.f16.f16.f32 "
        "{%0,%1,%2,%3}, {%4,%5,%6,%7}, {%8,%9}, {%0,%1,%2,%3};"
        : "+f"(d[0]), "+f"(d[1]), "+f"(d[2]), "+f"(d[3])
        : "r"(a[0]), "r"(a[1]), "r"(a[2]), "r"(a[3]), "r"(b[0]), "r"(b[1]));
}
__device__ __forceinline__ void ldsm4(uint32_t& r0, uint32_t& r1, uint32_t& r2,
                                      uint32_t& r3, uint32_t addr) {
    asm volatile("ldmatrix.sync.aligned.m8n8.x4.shared.b16 {%0,%1,%2,%3}, [%4];"
                 : "=r"(r0), "=r"(r1), "=r"(r2), "=r"(r3) : "r"(addr));
}
__device__ __forceinline__ void cpasync16(uint32_t s, const void* g) {
    asm volatile("cp.async.ca.shared.global [%0], [%1], 16;" :: "r"(s), "l"(g));
}
#define CP_COMMIT() asm volatile("cp.async.commit_group;" ::: "memory")
#define CP_WAIT(n)  asm volatile("cp.async.wait_group %0;" :: "n"(n) : "memory")

__device__ __forceinline__ float gelu1(float v) {
    return 0.5f * v * (1.0f + erff(v * 0.70710678118654752f));
}

// ---------------------------------------------------------------------------
// Weight split + transpose: w [K][N] fp32 -> whi/wlo [N][K] halves.
// One [32k x 64n] tile per block; blockIdx.z = matrix slice.
// ---------------------------------------------------------------------------
__global__ void __launch_bounds__(256) wsplitT(const float* __restrict__ w,
        __half* __restrict__ whi, __half* __restrict__ wlo, int K, int N)
{
    const size_t zoff = (size_t)blockIdx.z * K * N;
    w += zoff; whi += zoff; wlo += zoff;
    const int n0 = blockIdx.x * 64, k0 = blockIdx.y * 32;
    __shared__ float tile[32][65];
    const int t = threadIdx.x;
    #pragma unroll
    for (int i = 0; i < 8; i++) {
        const int e = t + i * 256;
        const int k = e >> 6, n = e & 63;
        tile[k][n] = w[(size_t)(k0 + k) * N + n0 + n];
    }
    __syncthreads();
    const int n = t >> 2, c = (t & 3) * 8;
    uint32_t hi[4], lo[4];
    #pragma unroll
    for (int i = 0; i < 4; i++)
        split2(tile[c + 2 * i][n], tile[c + 2 * i + 1][n], hi[i], lo[i]);
    const size_t o = (size_t)(n0 + n) * K + k0 + c;
    *(uint4*)&whi[o] = make_uint4(hi[0], hi[1], hi[2], hi[3]);
    *(uint4*)&wlo[o] = make_uint4(lo[0], lo[1], lo[2], lo[3]);
}

// ---------------------------------------------------------------------------
// hgemm: C[M,N] = epi(Ah+Al @ (Bh+Bl)^T + bias), operands pre-split halves.
// A [M][K], B [N][K] (transposed). Tile 64x128, BK=32, 256 thr, 3-stage
// cp.async pipeline, ldmatrix fragments, KST=40 smem rows.
// EPI: 0 store fp32, 3 C+=v, 5 atomic scatter C[idx[r]]+=rw[r]*v,
//      6 gelu -> write half hi/lo (Ch/Cl)
// ---------------------------------------------------------------------------
#define KST 40
#define HG_STG 15360   // halves per stage: A 2*2560 + B 2*5120
#define SMEM_HG (3 * HG_STG * 2)

template<int EPI, bool GA, bool GUARD, bool EXPZ>
__global__ void __launch_bounds__(256) hgemm(
    const __half* __restrict__ Ah, const __half* __restrict__ Al,
    const __half* __restrict__ Bh, const __half* __restrict__ Bl,
    const float* __restrict__ bias,
    float* __restrict__ C, __half* __restrict__ Ch, __half* __restrict__ Cl,
    int M, int N, int K,
    const int* __restrict__ idx, const float* __restrict__ rw,
    const int* __restrict__ cnt, size_t zA, size_t zC)
{
    if (EXPZ) {
        const int z = blockIdx.z;
        Ah += (size_t)z * zA; Al += (size_t)z * zA;
        Bh += (size_t)z * (size_t)K * N; Bl += (size_t)z * (size_t)K * N;
        bias += (size_t)z * N;
        if (EPI == 6) { Ch += (size_t)z * zC; Cl += (size_t)z * zC; }
        else          { C  += (size_t)z * zC; }
        idx += z * T_TOK;
        if (rw) rw += z * T_TOK;
        cnt += z;
    }
    const int t = threadIdx.x, wid = t >> 5, lane = t & 31;
    const int m0 = blockIdx.y * 64, n0 = blockIdx.x * 128;

    int cq = M;
    if (GUARD) { cq = *cnt; if (m0 >= cq) return; }

    extern __shared__ __half sh[];
    const uint32_t sbase = (uint32_t)__cvta_generic_to_shared(sh);

    // A loader: 1x16B hi + 1x16B lo per thread
    const int arow = t >> 2, acof = (t & 3) * 8;
    int garow = m0 + arow;
    if (GA) garow = (garow < cq) ? idx[garow] : idx[0];
    const __half* Asrc_h = Ah + (size_t)garow * K + acof;
    const __half* Asrc_l = Al + (size_t)garow * K + acof;
    // B loader: 2x16B hi + 2x16B lo per thread
    const int brow = t >> 1;
    const int bcof0 = ((2 * t) & 3) * 8, bcof1 = ((2 * t + 1) & 3) * 8;
    const __half* Bsrc_h = Bh + (size_t)(n0 + brow) * K;
    const __half* Bsrc_l = Bl + (size_t)(n0 + brow) * K;

    const uint32_t adst  = (uint32_t)(arow * KST + acof) * 2u;
    const uint32_t bdst0 = (uint32_t)(brow * KST + bcof0) * 2u;
    const uint32_t bdst1 = (uint32_t)(brow * KST + bcof1) * 2u;

    auto issue = [&](int s, int k0) {
        const uint32_t sb = sbase + (uint32_t)(s * HG_STG) * 2u;
        cpasync16(sb + adst,               Asrc_h + k0);
        cpasync16(sb + 2560u * 2u + adst,  Asrc_l + k0);
        cpasync16(sb + 5120u * 2u + bdst0, Bsrc_h + k0 + bcof0);
        cpasync16(sb + 5120u * 2u + bdst1, Bsrc_h + k0 + bcof1);
        cpasync16(sb + 10240u * 2u + bdst0, Bsrc_l + k0 + bcof0);
        cpasync16(sb + 10240u * 2u + bdst1, Bsrc_l + k0 + bcof1);
        CP_COMMIT();
    };

    // fragment addressing (validated layout)
    const int wm = wid >> 2, wn = wid & 3;
    const int gid = lane >> 2, tig = lane & 3;
    const int l7 = lane & 7, q8 = lane >> 3;
    const int A_row = (q8 & 1) * 8 + l7, A_k = (q8 >> 1) * 8;
    const int B_row = (q8 >> 1) * 8 + l7, B_k = (q8 & 1) * 8;
    const uint32_t aoff0 = (uint32_t)((wm * 32 + A_row) * KST + A_k) * 2u;
    const uint32_t aoff1 = aoff0 + 16u * KST * 2u;
    const uint32_t boff0 = (uint32_t)((wn * 32 + B_row) * KST + B_k) * 2u;
    const uint32_t boff1 = boff0 + 16u * KST * 2u;

    float acc[2][4][4] = {};

    const int nkt = K >> 5;
    issue(0, 0);
    issue(1, 32);
    for (int j = 0; j < nkt; j++) {
        if (j + 2 < nkt) { issue((j + 2) % 3, (j + 2) << 5); CP_WAIT(2); }
        else             { CP_WAIT(0); }
        __syncthreads();
        const uint32_t sb = sbase + (uint32_t)((j % 3) * HG_STG) * 2u;
        const uint32_t aHiB = sb, aLoB = sb + 2560u * 2u;
        const uint32_t bHiB = sb + 5120u * 2u, bLoB = sb + 10240u * 2u;
        #pragma unroll
        for (int ks = 0; ks < 2; ks++) {
            const uint32_t kadd = (uint32_t)ks * 32u;
            uint32_t bh[2][4], bl[2][4], ah[2][4], al[2][4];
            ldsm4(bh[0][0], bh[0][1], bh[0][2], bh[0][3], bHiB + boff0 + kadd);
            ldsm4(bh[1][0], bh[1][1], bh[1][2], bh[1][3], bHiB + boff1 + kadd);
            ldsm4(bl[0][0], bl[0][1], bl[0][2], bl[0][3], bLoB + boff0 + kadd);
            ldsm4(bl[1][0], bl[1][1], bl[1][2], bl[1][3], bLoB + boff1 + kadd);
            ldsm4(ah[0][0], ah[0][1], ah[0][2], ah[0][3], aHiB + aoff0 + kadd);
            ldsm4(ah[1][0], ah[1][1], ah[1][2], ah[1][3], aHiB + aoff1 + kadd);
            ldsm4(al[0][0], al[0][1], al[0][2], al[0][3], aLoB + aoff0 + kadd);
            ldsm4(al[1][0], al[1][1], al[1][2], al[1][3], aLoB + aoff1 + kadd);
            #pragma unroll
            for (int mi = 0; mi < 2; mi++)
                #pragma unroll
                for (int ni = 0; ni < 4; ni++)
                    mma_f16(acc[mi][ni], ah[mi], &bh[ni >> 1][(ni & 1) * 2]);
            #pragma unroll
            for (int mi = 0; mi < 2; mi++)
                #pragma unroll
                for (int ni = 0; ni < 4; ni++)
                    mma_f16(acc[mi][ni], ah[mi], &bl[ni >> 1][(ni & 1) * 2]);
            #pragma unroll
            for (int mi = 0; mi < 2; mi++)
                #pragma unroll
                for (int ni = 0; ni < 4; ni++)
                    mma_f16(acc[mi][ni], al[mi], &bh[ni >> 1][(ni & 1) * 2]);
        }
        __syncthreads();
    }

    #pragma unroll
    for (int mi = 0; mi < 2; mi++) {
        #pragma unroll
        for (int half = 0; half < 2; half++) {
            const int row = m0 + wm * 32 + mi * 16 + gid + half * 8;
            if (GUARD && row >= cq) continue;
            #pragma unroll
            for (int ni = 0; ni < 4; ni++) {
                const int col = n0 + wn * 32 + ni * 8 + tig * 2;
                float vx = acc[mi][ni][half * 2 + 0] + bias[col];
                float vy = acc[mi][ni][half * 2 + 1] + bias[col + 1];
                if (EPI == 5) {
                    const float w = rw[row];
                    float* dst = C + (size_t)idx[row] * N + col;
                    atomicAdd(dst,     w * vx);
                    atomicAdd(dst + 1, w * vy);
                } else if (EPI == 6) {
                    vx = gelu1(vx); vy = gelu1(vy);
                    uint32_t hi, lo;
                    split2(vx, vy, hi, lo);
                    *(uint32_t*)&Ch[(size_t)row * N + col] = hi;
                    *(uint32_t*)&Cl[(size_t)row * N + col] = lo;
                } else {
                    float* dst = C + (size_t)row * N + col;
                    if (EPI == 3) {
                        const float2 cc = *(const float2*)dst;
                        vx += cc.x; vy += cc.y;
                    }
                    *(float2*)dst = make_float2(vx, vy);
                }
            }
        }
    }
}

// ---------------------------------------------------------------------------
// Old fp32-input GEMM (front-end only). EPI: 0 store, 1 gelu, 2 res+v.
// ---------------------------------------------------------------------------
#define AH_SZ (64 * KST)
#define BH_SZ (128 * KST)
#define OFF_AH(b) ((b) * AH_SZ)
#define OFF_AL(b) (2 * AH_SZ + (b) * AH_SZ)
#define OFF_BH(b) (4 * AH_SZ + (b) * BH_SZ)
#define OFF_BL(b) (4 * AH_SZ + 2 * BH_SZ + (b) * BH_SZ)
#define SMEM_MMA ((4 * AH_SZ + 4 * BH_SZ) * 2)

template<int EPI>
__global__ void __launch_bounds__(256, 2) mma_gemm(
    const float* __restrict__ A, const float* __restrict__ B,
    const float* __restrict__ bias, float* __restrict__ C,
    int M, int N, int K, const float* __restrict__ res)
{
    const int t = threadIdx.x, wid = t >> 5, lane = t & 31;
    const int m0 = blockIdx.y * 64, n0 = blockIdx.x * 128;

    extern __shared__ __half sh[];
    const uint32_t sbase = (uint32_t)__cvta_generic_to_shared(sh);

    const int arow = t >> 2, akof = (t & 3) * 8;
    const float* Agp = A + (size_t)(m0 + arow) * K + akof;
    const int nB = t & 127, kk2 = t >> 7;
    const float* Bcol = B + n0 + nB;

    const int wm = wid >> 2, wn = wid & 3;
    const int gid = lane >> 2, tig = lane & 3;
    const int l7 = lane & 7, q8 = lane >> 3;
    const int A_row = (q8 & 1) * 8 + l7, A_k = (q8 >> 1) * 8;
    const int B_row = (q8 >> 1) * 8 + l7, B_k = (q8 & 1) * 8;
    const uint32_t aoff0 = (uint32_t)((wm * 32 + A_row) * KST + A_k) * 2u;
    const uint32_t aoff1 = aoff0 + 16u * KST * 2u;
    const uint32_t boff0 = (uint32_t)((wn * 32 + B_row) * KST + B_k) * 2u;
    const uint32_t boff1 = boff0 + 16u * KST * 2u;

    float4 pa0, pa1;
    float pb[16];

    pa0 = *(const float4*)(Agp);
    pa1 = *(const float4*)(Agp + 4);
    #pragma unroll
    for (int i = 0; i < 4; i++)
        #pragma unroll
        for (int jj = 0; jj < 4; jj++)
            pb[i * 4 + jj] = Bcol[(size_t)(kk2 * 16 + i * 4 + jj) * N];
    {
        uint32_t h0,l0,h1,l1,h2,l2,h3,l3;
        split2(pa0.x, pa0.y, h0, l0); split2(pa0.z, pa0.w, h1, l1);
        split2(pa1.x, pa1.y, h2, l2); split2(pa1.z, pa1.w, h3, l3);
        *(uint4*)&sh[OFF_AH(0) + arow * KST + akof] = make_uint4(h0,h1,h2,h3);
        *(uint4*)&sh[OFF_AL(0) + arow * KST + akof] = make_uint4(l0,l1,l2,l3);
        #pragma unroll
        for (int i = 0; i < 4; i++) {
            const int kb = kk2 * 16 + i * 4;
            uint32_t bh0,bl0,bh1,bl1;
            split2(pb[i*4+0], pb[i*4+1], bh0, bl0);
            split2(pb[i*4+2], pb[i*4+3], bh1, bl1);
            *(uint2*)&sh[OFF_BH(0) + nB * KST + kb] = make_uint2(bh0, bh1);
            *(uint2*)&sh[OFF_BL(0) + nB * KST + kb] = make_uint2(bl0, bl1);
        }
    }
    __syncthreads();

    float acc[2][4][4] = {};

    const int nkt = K >> 5;
    for (int j = 0; j < nkt; j++) {
        const int cur = j & 1;
        const bool more = (j + 1 < nkt);
        if (more) {
            const int k0 = (j + 1) << 5;
            pa0 = *(const float4*)(Agp + k0);
            pa1 = *(const float4*)(Agp + k0 + 4);
            #pragma unroll
            for (int i = 0; i < 4; i++)
                #pragma unroll
                for (int jj = 0; jj < 4; jj++)
                    pb[i * 4 + jj] = Bcol[(size_t)(k0 + kk2 * 16 + i * 4 + jj) * N];
        }
        {
            const uint32_t aHiB = sbase + (uint32_t)OFF_AH(cur) * 2u;
            const uint32_t aLoB = sbase + (uint32_t)OFF_AL(cur) * 2u;
            const uint32_t bHiB = sbase + (uint32_t)OFF_BH(cur) * 2u;
            const uint32_t bLoB = sbase + (uint32_t)OFF_BL(cur) * 2u;
            #pragma unroll
            for (int ks = 0; ks < 2; ks++) {
                const uint32_t kadd = (uint32_t)ks * 32u;
                uint32_t bh[2][4], bl[2][4], ah[2][4], al[2][4];
                ldsm4(bh[0][0], bh[0][1], bh[0][2], bh[0][3], bHiB + boff0 + kadd);
                ldsm4(bh[1][0], bh[1][1], bh[1][2], bh[1][3], bHiB + boff1 + kadd);
                ldsm4(bl[0][0], bl[0][1], bl[0][2], bl[0][3], bLoB + boff0 + kadd);
                ldsm4(bl[1][0], bl[1][1], bl[1][2], bl[1][3], bLoB + boff1 + kadd);
                ldsm4(ah[0][0], ah[0][1], ah[0][2], ah[0][3], aHiB + aoff0 + kadd);
                ldsm4(ah[1][0], ah[1][1], ah[1][2], ah[1][3], aHiB + aoff1 + kadd);
                ldsm4(al[0][0], al[0][1], al[0][2], al[0][3], aLoB + aoff0 + kadd);
                ldsm4(al[1][0], al[1][1], al[1][2], al[1][3], aLoB + aoff1 + kadd);
                #pragma unroll
                for (int mi = 0; mi < 2; mi++)
                    #pragma unroll
                    for (int ni = 0; ni < 4; ni++)
                        mma_f16(acc[mi][ni], ah[mi], &bh[ni >> 1][(ni & 1) * 2]);
                #pragma unroll
                for (int mi = 0; mi < 2; mi++)
                    #pragma unroll
                    for (int ni = 0; ni < 4; ni++)
                        mma_f16(acc[mi][ni], ah[mi], &bl[ni >> 1][(ni & 1) * 2]);
                #pragma unroll
                for (int mi = 0; mi < 2; mi++)
                    #pragma unroll
                    for (int ni = 0; ni < 4; ni++)
                        mma_f16(acc[mi][ni], al[mi], &bh[ni >> 1][(ni & 1) * 2]);
            }
        }
        if (more) {
            const int nxt = cur ^ 1;
            uint32_t h0,l0,h1,l1,h2,l2,h3,l3;
            split2(pa0.x, pa0.y, h0, l0); split2(pa0.z, pa0.w, h1, l1);
            split2(pa1.x, pa1.y, h2, l2); split2(pa1.z, pa1.w, h3, l3);
            *(uint4*)&sh[OFF_AH(nxt) + arow * KST + akof] = make_uint4(h0,h1,h2,h3);
            *(uint4*)&sh[OFF_AL(nxt) + arow * KST + akof] = make_uint4(l0,l1,l2,l3);
            #pragma unroll
            for (int i = 0; i < 4; i++) {
                const int kb = kk2 * 16 + i * 4;
                uint32_t bh0,bl0,bh1,bl1;
                split2(pb[i*4+0], pb[i*4+1], bh0, bl0);
                split2(pb[i*4+2], pb[i*4+3], bh1, bl1);
                *(uint2*)&sh[OFF_BH(nxt) + nB * KST + kb] = make_uint2(bh0, bh1);
                *(uint2*)&sh[OFF_BL(nxt) + nB * KST + kb] = make_uint2(bl0, bl1);
            }
            __syncthreads();
        }
    }

    #pragma unroll
    for (int mi = 0; mi < 2; mi++) {
        #pragma unroll
        for (int half = 0; half < 2; half++) {
            const int row = m0 + wm * 32 + mi * 16 + gid + half * 8;
            #pragma unroll
            for (int ni = 0; ni < 4; ni++) {
                const int col = n0 + wn * 32 + ni * 8 + tig * 2;
                float vx = acc[mi][ni][half * 2 + 0] + bias[col];
                float vy = acc[mi][ni][half * 2 + 1] + bias[col + 1];
                float* dst = C + (size_t)row * N + col;
                if (EPI == 1) {
                    vx = gelu1(vx); vy = gelu1(vy);
                } else if (EPI == 2) {
                    const float2 rr = *(const float2*)(res + (size_t)row * N + col);
                    vx += rr.x; vy += rr.y;
                }
                *(float2*)dst = make_float2(vx, vy);
            }
        }
    }
}

// ---------------------------------------------------------------------------
// Flash attention: block per (b,head), thread per query row; writes HALVES.
// ---------------------------------------------------------------------------
#define KVP 68
#define SMEM_ATTN (2 * 128 * KVP * 4)

__global__ void __launch_bounds__(128) attn_flash(const float* __restrict__ qkv,
                                                  __half* __restrict__ oh,
                                                  __half* __restrict__ ol)
{
    const int bh = blockIdx.x;
    const int b = bh >> 3, hh = bh & 7;
    const int t = threadIdx.x;
    const float* base = qkv + (size_t)b * 128 * 1536 + hh * 64;

    extern __shared__ float kv[];
    float (*Ks)[KVP] = (float(*)[KVP])kv;
    float (*Vs)[KVP] = (float(*)[KVP])(kv + 128 * KVP);

    {
        const float* kr = base + (size_t)t * 1536 + 512;
        const float* vr = kr + 512;
        #pragma unroll
        for (int d4 = 0; d4 < 16; d4++) {
            *(float4*)&Ks[t][d4 * 4] = *(const float4*)(kr + d4 * 4);
            *(float4*)&Vs[t][d4 * 4] = *(const float4*)(vr + d4 * 4);
        }
    }
    float q[64];
    {
        const float* qr = base + (size_t)t * 1536;
        #pragma unroll
        for (int d4 = 0; d4 < 16; d4++) {
            float4 f = *(const float4*)(qr + d4 * 4);
            q[d4 * 4 + 0] = f.x; q[d4 * 4 + 1] = f.y;
            q[d4 * 4 + 2] = f.z; q[d4 * 4 + 3] = f.w;
        }
    }
    __syncthreads();

    float oacc[64];
    #pragma unroll
    for (int d = 0; d < 64; d++) oacc[d] = 0.f;
    float m = -1e30f, l = 0.f;

    for (int j = 0; j <= t; j++) {
        float s = 0.f;
        #pragma unroll
        for (int d4 = 0; d4 < 16; d4++) {
            float4 k4 = *(const float4*)&Ks[j][d4 * 4];
            s += q[d4 * 4 + 0] * k4.x + q[d4 * 4 + 1] * k4.y
               + q[d4 * 4 + 2] * k4.z + q[d4 * 4 + 3] * k4.w;
        }
        s *= 0.125f;
        const float nm = fmaxf(m, s);
        const float sc = __expf(m - nm), e = __expf(s - nm);
        l = l * sc + e;
        m = nm;
        #pragma unroll
        for (int d4 = 0; d4 < 16; d4++) {
            float4 v4 = *(const float4*)&Vs[j][d4 * 4];
            oacc[d4 * 4 + 0] = oacc[d4 * 4 + 0] * sc + e * v4.x;
            oacc[d4 * 4 + 1] = oacc[d4 * 4 + 1] * sc + e * v4.y;
            oacc[d4 * 4 + 2] = oacc[d4 * 4 + 2] * sc + e * v4.z;
            oacc[d4 * 4 + 3] = oacc[d4 * 4 + 3] * sc + e * v4.w;
        }
    }
    const float inv = 1.0f / l;
    const size_t oo = ((size_t)b * 128 + t) * 512 + hh * 64;
    #pragma unroll
    for (int d4 = 0; d4 < 16; d4++) {
        uint32_t h0, l0, h1, l1;
        split2(oacc[d4 * 4 + 0] * inv, oacc[d4 * 4 + 1] * inv, h0, l0);
        split2(oacc[d4 * 4 + 2] * inv, oacc[d4 * 4 + 3] * inv, h1, l1);
        *(uint2*)&oh[oo + d4 * 4] = make_uint2(h0, h1);
        *(uint2*)&ol[oo + d4 * 4] = make_uint2(l0, l1);
    }
}

// ---------------------------------------------------------------------------
__global__ void patchnorm_kernel(const float* __restrict__ x, float* __restrict__ y)
{
    const int warp = threadIdx.x >> 5, lane = threadIdx.x & 31;
    const int row = blockIdx.x * 8 + warp;
    const float* xr = x + (size_t)row * 128;
    float4 f = *(const float4*)(xr + lane * 4);
    float s = f.x + f.y + f.z + f.w;
    #pragma unroll
    for (int o = 16; o; o >>= 1) s += __shfl_xor_sync(0xffffffffu, s, o);
    const float mu = s * (1.0f / 128.0f);
    float q = (f.x - mu) * (f.x - mu) + (f.y - mu) * (f.y - mu)
            + (f.z - mu) * (f.z - mu) + (f.w - mu) * (f.w - mu);
    #pragma unroll
    for (int o = 16; o; o >>= 1) q += __shfl_xor_sync(0xffffffffu, q, o);
    const float rs = rsqrtf(q * (1.0f / 128.0f) + 1e-6f);
    float4 r = make_float4((f.x - mu) * rs, (f.y - mu) * rs, (f.z - mu) * rs, (f.w - mu) * rs);
    *(float4*)(y + (size_t)row * 128 + lane * 4) = r;
}

// LayerNorm over 512; writes fp32 y AND half hi/lo yh/yl.
__global__ void ln512d_kernel(const float* __restrict__ x, float* __restrict__ y,
                              __half* __restrict__ yh, __half* __restrict__ yl,
                              const float* __restrict__ g, const float* __restrict__ b)
{
    const int warp = threadIdx.x >> 5, lane = threadIdx.x & 31;
    const int row = blockIdx.x * 8 + warp;
    const float* xr = x + (size_t)row * 512;
    float v[16];
    float s = 0.f;
    #pragma unroll
    for (int c = 0; c < 4; c++) {
        float4 f = *(const float4*)(xr + c * 128 + lane * 4);
        v[c * 4 + 0] = f.x; v[c * 4 + 1] = f.y; v[c * 4 + 2] = f.z; v[c * 4 + 3] = f.w;
        s += f.x + f.y + f.z + f.w;
    }
    #pragma unroll
    for (int o = 16; o; o >>= 1) s += __shfl_xor_sync(0xffffffffu, s, o);
    const float mu = s * (1.0f / 512.0f);
    float q = 0.f;
    #pragma unroll
    for (int k = 0; k < 16; k++) { float d = v[k] - mu; q += d * d; }
    #pragma unroll
    for (int o = 16; o; o >>= 1) q += __shfl_xor_sync(0xffffffffu, q, o);
    const float rs = rsqrtf(q * (1.0f / 512.0f) + 1e-5f);
    #pragma unroll
    for (int c = 0; c < 4; c++) {
        const int col = c * 128 + lane * 4;
        float4 gg = *(const float4*)(g + col);
        float4 bb = *(const float4*)(b + col);
        float4 r;
        r.x = gg.x * (v[c * 4 + 0] - mu) * rs + bb.x;
        r.y = gg.y * (v[c * 4 + 1] - mu) * rs + bb.y;
        r.z = gg.z * (v[c * 4 + 2] - mu) * rs + bb.z;
        r.w = gg.w * (v[c * 4 + 3] - mu) * rs + bb.w;
        *(float4*)(y + (size_t)row * 512 + col) = r;
        uint32_t h0, l0, h1, l1;
        split2(r.x, r.y, h0, l0);
        split2(r.z, r.w, h1, l1);
        *(uint2*)&yh[(size_t)row * 512 + col] = make_uint2(h0, h1);
        *(uint2*)&yl[(size_t)row * 512 + col] = make_uint2(l0, l1);
    }
}

__global__ void freqadd_kernel(float* __restrict__ h, const float* __restrict__ emb,
                               const int* __restrict__ fid)
{
    const int i = blockIdx.x * 256 + threadIdx.x;
    const int row = i >> 9, d = i & 511, b = row >> 7;
    h[i] += emb[(size_t)fid[b] * 512 + d];
}

__global__ void zero_cnt_kernel(int* cnt)
{
    if (threadIdx.x < 4) cnt[threadIdx.x] = 0;
}

__global__ void gate_route_kernel(const float* __restrict__ hn, const float* __restrict__ gw,
                                  const float* __restrict__ gb,
                                  int* __restrict__ cnt, int* __restrict__ idx,
                                  float* __restrict__ rw)
{
    const int warp = threadIdx.x >> 5, lane = threadIdx.x & 31;
    const int row = blockIdx.x * 8 + warp;
    const float* xr = hn + (size_t)row * 512;
    float a0 = 0.f, a1 = 0.f, a2 = 0.f, a3 = 0.f;
    for (int d = lane; d < 512; d += 32) {
        const float hv = xr[d];
        float4 w = *(const float4*)(gw + (size_t)d * 4);
        a0 += hv * w.x; a1 += hv * w.y; a2 += hv * w.z; a3 += hv * w.w;
    }
    #pragma unroll
    for (int o = 16; o; o >>= 1) {
        a0 += __shfl_xor_sync(0xffffffffu, a0, o);
        a1 += __shfl_xor_sync(0xffffffffu, a1, o);
        a2 += __shfl_xor_sync(0xffffffffu, a2, o);
        a3 += __shfl_xor_sync(0xffffffffu, a3, o);
    }
    if (lane == 0) {
        float p[4] = {a0 + gb[0], a1 + gb[1], a2 + gb[2], a3 + gb[3]};
        const float mx = fmaxf(fmaxf(p[0], p[1]), fmaxf(p[2], p[3]));
        float s = 0.f;
        #pragma unroll
        for (int e = 0; e < 4; e++) { p[e] = expf(p[e] - mx); s += p[e]; }
        const float invs = 1.0f / s;
        #pragma unroll
        for (int e = 0; e < 4; e++) p[e] *= invs;
        int i0 = 0;
        #pragma unroll
        for (int e = 1; e < 4; e++) if (p[e] > p[i0]) i0 = e;
        int i1 = -1;
        #pragma unroll
        for (int e = 0; e < 4; e++) if (e != i0 && (i1 < 0 || p[e] > p[i1])) i1 = e;
        int s0 = atomicAdd(&cnt[i0], 1);
        idx[i0 * T_TOK + s0] = row; rw[i0 * T_TOK + s0] = p[i0];
        int s1 = atomicAdd(&cnt[i1], 1);
        idx[i1 * T_TOK + s1] = row; rw[i1 * T_TOK + s1] = p[i1];
    }
}

__global__ void head_kernel(const float* __restrict__ h,
                            const float* __restrict__ fng, const float* __restrict__ fnb,
                            const float* __restrict__ hg,  const float* __restrict__ hb,
                            const float* __restrict__ hw,  const float* __restrict__ hbias,
                            float* __restrict__ out, int out_size)
{
    const int warp = threadIdx.x >> 5, lane = threadIdx.x & 31;
    const int b = warp;
    const float* xr = h + ((size_t)b * 128 + 127) * 512;
    float v[16];
    float s = 0.f;
    #pragma unroll
    for (int c = 0; c < 4; c++) {
        float4 f = *(const float4*)(xr + c * 128 + lane * 4);
        v[c * 4 + 0] = f.x; v[c * 4 + 1] = f.y; v[c * 4 + 2] = f.z; v[c * 4 + 3] = f.w;
        s += f.x + f.y + f.z + f.w;
    }
    #pragma unroll
    for (int o = 16; o; o >>= 1) s += __shfl_xor_sync(0xffffffffu, s, o);
    float mu = s * (1.0f / 512.0f);
    float q = 0.f;
    #pragma unroll
    for (int k = 0; k < 16; k++) { float d = v[k] - mu; q += d * d; }
    #pragma unroll
    for (int o = 16; o; o >>= 1) q += __shfl_xor_sync(0xffffffffu, q, o);
    float rs = rsqrtf(q * (1.0f / 512.0f) + 1e-5f);
    #pragma unroll
    for (int c = 0; c < 4; c++)
        #pragma unroll
        for (int j = 0; j < 4; j++) {
            const int col = c * 128 + lane * 4 + j;
            v[c * 4 + j] = fng[col] * (v[c * 4 + j] - mu) * rs + fnb[col];
        }
    s = 0.f;
    #pragma unroll
    for (int k = 0; k < 16; k++) s += v[k];
    #pragma unroll
    for (int o = 16; o; o >>= 1) s += __shfl_xor_sync(0xffffffffu, s, o);
    mu = s * (1.0f / 512.0f);
    q = 0.f;
    #pragma unroll
    for (int k = 0; k < 16; k++) { float d = v[k] - mu; q += d * d; }
    #pragma unroll
    for (int o = 16; o; o >>= 1) q += __shfl_xor_sync(0xffffffffu, q, o);
    rs = rsqrtf(q * (1.0f / 512.0f) + 1e-5f);
    float dot = 0.f;
    #pragma unroll
    for (int c = 0; c < 4; c++)
        #pragma unroll
        for (int j = 0; j < 4; j++) {
            const int col = c * 128 + lane * 4 + j;
            const float hl = hg[col] * (v[c * 4 + j] - mu) * rs + hb[col];
            dot += hl * hw[col];
        }
    #pragma unroll
    for (int o = 16; o; o >>= 1) dot += __shfl_xor_sync(0xffffffffu, dot, o);
    if (lane == 0) {
        const float logit = dot + hbias[0];
        if (out_size >= 32) {
            out[b] = logit;
            out[16 + b] = 1.0f / (1.0f + expf(-logit));
        } else {
            out[b] = logit;
        }
    }
}

// ---------------------------------------------------------------------------
extern "C" void kernel_launch(void* const* d_in, const int* in_sizes, int n_in,
                              void* d_out, int out_size)
{
    const float* x        = (const float*)d_in[0];
    const int*   fid      = (const int*)  d_in[1];
    const float* ir_w1    = (const float*)d_in[2];
    const float* ir_b1    = (const float*)d_in[3];
    const float* ir_w2    = (const float*)d_in[4];
    const float* ir_b2    = (const float*)d_in[5];
    const float* p2m_w    = (const float*)d_in[6];
    const float* p2m_b    = (const float*)d_in[7];
    const float* freq_emb = (const float*)d_in[8];
    const float* ln1_g    = (const float*)d_in[9];
    const float* ln1_b    = (const float*)d_in[10];
    const float* qkv_w    = (const float*)d_in[11];
    const float* qkv_b    = (const float*)d_in[12];
    const float* out_w    = (const float*)d_in[13];
    const float* out_b    = (const float*)d_in[14];
    const float* ln2_g    = (const float*)d_in[15];
    const float* ln2_b    = (const float*)d_in[16];
    const float* gate_w   = (const float*)d_in[17];
    const float* gate_b   = (const float*)d_in[18];
    const float* exp_w1   = (const float*)d_in[19];
    const float* exp_b1   = (const float*)d_in[20];
    const float* exp_w2   = (const float*)d_in[21];
    const float* exp_b2   = (const float*)d_in[22];
    const float* fn_g     = (const float*)d_in[23];
    const float* fn_b     = (const float*)d_in[24];
    const float* head_g   = (const float*)d_in[25];
    const float* head_b   = (const float*)d_in[26];
    const float* head_w   = (const float*)d_in[27];
    const float* head_bias= (const float*)d_in[28];

    float *patches, *tmp, *hp, *h, *hn, *qkv, *rw;
    int *cnt, *idx;
    __half *qkvTh, *qkvTl, *outTh, *outTl, *e1Th, *e1Tl, *e2Th, *e2Tl;
    __half *hnh, *hnl, *ath, *atl, *ehh, *ehl;
    cudaGetSymbolAddress((void**)&patches, g_patches);
    cudaGetSymbolAddress((void**)&tmp,     g_tmp);
    cudaGetSymbolAddress((void**)&hp,      g_hp);
    cudaGetSymbolAddress((void**)&h,       g_h);
    cudaGetSymbolAddress((void**)&hn,      g_hn);
    cudaGetSymbolAddress((void**)&qkv,     g_qkv);
    cudaGetSymbolAddress((void**)&cnt,     g_cnt);
    cudaGetSymbolAddress((void**)&idx,     g_idx);
    cudaGetSymbolAddress((void**)&rw,      g_rw);
    cudaGetSymbolAddress((void**)&qkvTh,   g_qkvTh);
    cudaGetSymbolAddress((void**)&qkvTl,   g_qkvTl);
    cudaGetSymbolAddress((void**)&outTh,   g_outTh);
    cudaGetSymbolAddress((void**)&outTl,   g_outTl);
    cudaGetSymbolAddress((void**)&e1Th,    g_e1Th);
    cudaGetSymbolAddress((void**)&e1Tl,    g_e1Tl);
    cudaGetSymbolAddress((void**)&e2Th,    g_e2Th);
    cudaGetSymbolAddress((void**)&e2Tl,    g_e2Tl);
    cudaGetSymbolAddress((void**)&hnh,     g_hnh);
    cudaGetSymbolAddress((void**)&hnl,     g_hnl);
    cudaGetSymbolAddress((void**)&ath,     g_ath);
    cudaGetSymbolAddress((void**)&atl,     g_atl);
    cudaGetSymbolAddress((void**)&ehh,     g_ehh);
    cudaGetSymbolAddress((void**)&ehl,     g_ehl);

    cudaFuncSetAttribute(mma_gemm<0>, cudaFuncAttributeMaxDynamicSharedMemorySize, SMEM_MMA);
    cudaFuncSetAttribute(mma_gemm<1>, cudaFuncAttributeMaxDynamicSharedMemorySize, SMEM_MMA);
    cudaFuncSetAttribute(mma_gemm<2>, cudaFuncAttributeMaxDynamicSharedMemorySize, SMEM_MMA);
    cudaFuncSetAttribute(hgemm<0,false,false,false>, cudaFuncAttributeMaxDynamicSharedMemorySize, SMEM_HG);
    cudaFuncSetAttribute(hgemm<3,false,false,false>, cudaFuncAttributeMaxDynamicSharedMemorySize, SMEM_HG);
    cudaFuncSetAttribute(hgemm<6,true,true,true>,    cudaFuncAttributeMaxDynamicSharedMemorySize, SMEM_HG);
    cudaFuncSetAttribute(hgemm<5,false,true,true>,   cudaFuncAttributeMaxDynamicSharedMemorySize, SMEM_HG);
    cudaFuncSetAttribute(attn_flash, cudaFuncAttributeMaxDynamicSharedMemorySize, SMEM_ATTN);

    // ---- pre-split all weights (hi/lo halves, transposed [N][K]) ----
    wsplitT<<<dim3(24, 16, 12), 256>>>(qkv_w,  qkvTh, qkvTl, 512, 1536);
    wsplitT<<<dim3(8,  16, 12), 256>>>(out_w,  outTh, outTl, 512, 512);
    wsplitT<<<dim3(32, 16, 48), 256>>>(exp_w1, e1Th,  e1Tl,  512, 2048);
    wsplitT<<<dim3(8,  64, 48), 256>>>(exp_w2, e2Th,  e2Tl,  2048, 512);

    // ---- front end (fp32 path) ----
    patchnorm_kernel<<<256, 256>>>(x, patches);
    mma_gemm<1><<<dim3(4, 32), 256, SMEM_MMA>>>(patches, ir_w1, ir_b1, tmp,
        T_TOK, 512, 128, nullptr);
    mma_gemm<2><<<dim3(1, 32), 256, SMEM_MMA>>>(tmp, ir_w2, ir_b2, hp,
        T_TOK, 128, 512, patches);
    mma_gemm<0><<<dim3(4, 32), 256, SMEM_MMA>>>(hp, p2m_w, p2m_b, h,
        T_TOK, 512, 128, nullptr);
    freqadd_kernel<<<(T_TOK * 512) / 256, 256>>>(h, freq_emb, fid);

    const size_t EHZ = (size_t)T_TOK * HDIM;

    for (int l = 0; l < 12; l++) {
        // attention
        ln512d_kernel<<<256, 256>>>(h, hn, hnh, hnl,
                                    ln1_g + (size_t)l * 512, ln1_b + (size_t)l * 512);
        hgemm<0,false,false,false><<<dim3(12, 32), 256, SMEM_HG>>>(
            hnh, hnl, qkvTh + (size_t)l * 1536 * 512, qkvTl + (size_t)l * 1536 * 512,
            qkv_b + (size_t)l * 1536, qkv, nullptr, nullptr,
            T_TOK, 1536, 512, nullptr, nullptr, nullptr, 0, 0);
        attn_flash<<<128, 128, SMEM_ATTN>>>(qkv, ath, atl);
        hgemm<3,false,false,false><<<dim3(4, 32), 256, SMEM_HG>>>(
            ath, atl, outTh + (size_t)l * 512 * 512, outTl + (size_t)l * 512 * 512,
            out_b + (size_t)l * 512, h, nullptr, nullptr,
            T_TOK, 512, 512, nullptr, nullptr, nullptr, 0, 0);
        // sparse MoE
        ln512d_kernel<<<256, 256>>>(h, hn, hnh, hnl,
                                    ln2_g + (size_t)l * 512, ln2_b + (size_t)l * 512);
        zero_cnt_kernel<<<1, 32>>>(cnt);
        gate_route_kernel<<<256, 256>>>(hn, gate_w + (size_t)l * 512 * 4,
                                        gate_b + (size_t)l * 4, cnt, idx, rw);
        hgemm<6,true,true,true><<<dim3(16, 32, 4), 256, SMEM_HG>>>(
            hnh, hnl, e1Th + (size_t)l * 4 * 2048 * 512, e1Tl + (size_t)l * 4 * 2048 * 512,
            exp_b1 + (size_t)l * 4 * 2048, nullptr, ehh, ehl,
            T_TOK, 2048, 512, idx, nullptr, cnt, 0, EHZ);
        hgemm<5,false,true,true><<<dim3(4, 32, 4), 256, SMEM_HG>>>(
            ehh, ehl, e2Th + (size_t)l * 4 * 512 * 2048, e2Tl + (size_t)l * 4 * 512 * 2048,
            exp_b2 + (size_t)l * 4 * 512, h, nullptr, nullptr,
            T_TOK, 512, 2048, idx, rw, cnt, EHZ, 0);
    }

    head_kernel<<<1, 512>>>(h, fn_g, fn_b, head_g, head_b, head_w, head_bias,
                            (float*)d_out, out_size);
}

// round 14
// speedup vs baseline: 1.0483x; 1.0483x over previous
#include <cuda_runtime.h>
#include <cuda_fp16.h>
#include <math.h>
#include <stdint.h>

// ---------------------------------------------------------------------------
// B=16, S=2048, C=8, P=16 -> N=128 patches, T=2048 tokens
// PD=128, IRH=512, D=512, NH=8, dh=64, L=12, E=4, H=2048, top-2 routing
// Split-precision fp16 HMMA GEMMs with PRE-SPLIT hi/lo operands; hgemm uses
// 2-stage cp.async + ldmatrix + mma at 2 CTAs/SM (4 warps/SMSP).
// ---------------------------------------------------------------------------
#define T_TOK 2048
#define DIM   512
#define HDIM  2048

__device__ float g_patches[T_TOK * 128];
__device__ float g_tmp    [T_TOK * 512];
__device__ float g_hp     [T_TOK * 128];
__device__ float g_h      [T_TOK * DIM];
__device__ float g_hn     [T_TOK * DIM];
__device__ float g_qkv    [T_TOK * 3 * DIM];
__device__ int   g_cnt    [4];
__device__ int   g_idx    [4 * T_TOK];
__device__ float g_rw     [4 * T_TOK];

// pre-split halves: weights (transposed [N][K]) + activations
__device__ __half g_qkvTh[12 * 1536 * 512];
__device__ __half g_qkvTl[12 * 1536 * 512];
__device__ __half g_outTh[12 * 512 * 512];
__device__ __half g_outTl[12 * 512 * 512];
__device__ __half g_e1Th [48 * 2048 * 512];
__device__ __half g_e1Tl [48 * 2048 * 512];
__device__ __half g_e2Th [48 * 512 * 2048];
__device__ __half g_e2Tl [48 * 512 * 2048];
__device__ __half g_hnh  [T_TOK * 512];
__device__ __half g_hnl  [T_TOK * 512];
__device__ __half g_ath  [T_TOK * 512];
__device__ __half g_atl  [T_TOK * 512];
__device__ __half g_ehh  [4 * T_TOK * 2048];
__device__ __half g_ehl  [4 * T_TOK * 2048];

// ---- helpers ---------------------------------------------------------------
__device__ __forceinline__ void split2(float f0, float f1, uint32_t& hi, uint32_t& lo) {
    __half2 h = __floats2half2_rn(f0, f1);
    float2 hf = __half22float2(h);
    __half2 l = __floats2half2_rn(f0 - hf.x, f1 - hf.y);
    hi = *(uint32_t*)&h;
    lo = *(uint32_t*)&l;
}
__device__ __forceinline__ void mma_f16(float* d, const uint32_t* a, const uint32_t* b) {
    asm volatile(
        "mma.sync.aligned.m16n8k16.row.col.f32.f16.f16.f32 "
        "{%0,%1,%2,%3}, {%4,%5,%6,%7}, {%8,%9}, {%0,%1,%2,%3};"
        : "+f"(d[0]), "+f"(d[1]), "+f"(d[2]), "+f"(d[3])
        : "r"(a[0]), "r"(a[1]), "r"(a[2]), "r"(a[3]), "r"(b[0]), "r"(b[1]));
}
__device__ __forceinline__ void ldsm4(uint32_t& r0, uint32_t& r1, uint32_t& r2,
                                      uint32_t& r3, uint32_t addr) {
    asm volatile("ldmatrix.sync.aligned.m8n8.x4.shared.b16 {%0,%1,%2,%3}, [%4];"
                 : "=r"(r0), "=r"(r1), "=r"(r2), "=r"(r3) : "r"(addr));
}
__device__ __forceinline__ void cpasync16(uint32_t s, const void* g) {
    asm volatile("cp.async.ca.shared.global [%0], [%1], 16;" :: "r"(s), "l"(g));
}
#define CP_COMMIT() asm volatile("cp.async.commit_group;" ::: "memory")
#define CP_WAIT(n)  asm volatile("cp.async.wait_group %0;" :: "n"(n) : "memory")

__device__ __forceinline__ float gelu1(float v) {
    return 0.5f * v * (1.0f + erff(v * 0.70710678118654752f));
}

// ---------------------------------------------------------------------------
// Weight split + transpose: w [K][N] fp32 -> whi/wlo [N][K] halves.
// ---------------------------------------------------------------------------
__global__ void __launch_bounds__(256) wsplitT(const float* __restrict__ w,
        __half* __restrict__ whi, __half* __restrict__ wlo, int K, int N)
{
    const size_t zoff = (size_t)blockIdx.z * K * N;
    w += zoff; whi += zoff; wlo += zoff;
    const int n0 = blockIdx.x * 64, k0 = blockIdx.y * 32;
    __shared__ float tile[32][65];
    const int t = threadIdx.x;
    #pragma unroll
    for (int i = 0; i < 8; i++) {
        const int e = t + i * 256;
        const int k = e >> 6, n = e & 63;
        tile[k][n] = w[(size_t)(k0 + k) * N + n0 + n];
    }
    __syncthreads();
    const int n = t >> 2, c = (t & 3) * 8;
    uint32_t hi[4], lo[4];
    #pragma unroll
    for (int i = 0; i < 4; i++)
        split2(tile[c + 2 * i][n], tile[c + 2 * i + 1][n], hi[i], lo[i]);
    const size_t o = (size_t)(n0 + n) * K + k0 + c;
    *(uint4*)&whi[o] = make_uint4(hi[0], hi[1], hi[2], hi[3]);
    *(uint4*)&wlo[o] = make_uint4(lo[0], lo[1], lo[2], lo[3]);
}

// ---------------------------------------------------------------------------
// hgemm: pre-split halves, 64x128 tile, BK=32, 2-stage cp.async, 2 CTAs/SM.
// EPI: 0 store fp32, 3 C+=v, 5 atomic scatter, 6 gelu -> half hi/lo
// ---------------------------------------------------------------------------
#define KST 40
#define HG_STG 15360                 // halves per stage
#define SMEM_HG (2 * HG_STG * 2)     // 61440 bytes

template<int EPI, bool GA, bool GUARD, bool EXPZ>
__global__ void __launch_bounds__(256, 2) hgemm(
    const __half* __restrict__ Ah, const __half* __restrict__ Al,
    const __half* __restrict__ Bh, const __half* __restrict__ Bl,
    const float* __restrict__ bias,
    float* __restrict__ C, __half* __restrict__ Ch, __half* __restrict__ Cl,
    int M, int N, int K,
    const int* __restrict__ idx, const float* __restrict__ rw,
    const int* __restrict__ cnt, size_t zA, size_t zC)
{
    if (EXPZ) {
        const int z = blockIdx.z;
        Ah += (size_t)z * zA; Al += (size_t)z * zA;
        Bh += (size_t)z * (size_t)K * N; Bl += (size_t)z * (size_t)K * N;
        bias += (size_t)z * N;
        if (EPI == 6) { Ch += (size_t)z * zC; Cl += (size_t)z * zC; }
        else          { C  += (size_t)z * zC; }
        idx += z * T_TOK;
        if (rw) rw += z * T_TOK;
        cnt += z;
    }
    const int t = threadIdx.x, wid = t >> 5, lane = t & 31;
    const int m0 = blockIdx.y * 64, n0 = blockIdx.x * 128;

    int cq = M;
    if (GUARD) { cq = *cnt; if (m0 >= cq) return; }

    extern __shared__ __half sh[];
    const uint32_t sbase = (uint32_t)__cvta_generic_to_shared(sh);

    const int arow = t >> 2, acof = (t & 3) * 8;
    int garow = m0 + arow;
    if (GA) garow = (garow < cq) ? idx[garow] : idx[0];
    const __half* Asrc_h = Ah + (size_t)garow * K + acof;
    const __half* Asrc_l = Al + (size_t)garow * K + acof;
    const int brow = t >> 1;
    const int bcof0 = ((2 * t) & 3) * 8, bcof1 = ((2 * t + 1) & 3) * 8;
    const __half* Bsrc_h = Bh + (size_t)(n0 + brow) * K;
    const __half* Bsrc_l = Bl + (size_t)(n0 + brow) * K;

    const uint32_t adst  = (uint32_t)(arow * KST + acof) * 2u;
    const uint32_t bdst0 = (uint32_t)(brow * KST + bcof0) * 2u;
    const uint32_t bdst1 = (uint32_t)(brow * KST + bcof1) * 2u;

    auto issue = [&](int s, int k0) {
        const uint32_t sb = sbase + (uint32_t)(s * HG_STG) * 2u;
        cpasync16(sb + adst,               Asrc_h + k0);
        cpasync16(sb + 2560u * 2u + adst,  Asrc_l + k0);
        cpasync16(sb + 5120u * 2u + bdst0, Bsrc_h + k0 + bcof0);
        cpasync16(sb + 5120u * 2u + bdst1, Bsrc_h + k0 + bcof1);
        cpasync16(sb + 10240u * 2u + bdst0, Bsrc_l + k0 + bcof0);
        cpasync16(sb + 10240u * 2u + bdst1, Bsrc_l + k0 + bcof1);
        CP_COMMIT();
    };

    const int wm = wid >> 2, wn = wid & 3;
    const int gid = lane >> 2, tig = lane & 3;
    const int l7 = lane & 7, q8 = lane >> 3;
    const int A_row = (q8 & 1) * 8 + l7, A_k = (q8 >> 1) * 8;
    const int B_row = (q8 >> 1) * 8 + l7, B_k = (q8 & 1) * 8;
    const uint32_t aoff0 = (uint32_t)((wm * 32 + A_row) * KST + A_k) * 2u;
    const uint32_t aoff1 = aoff0 + 16u * KST * 2u;
    const uint32_t boff0 = (uint32_t)((wn * 32 + B_row) * KST + B_k) * 2u;
    const uint32_t boff1 = boff0 + 16u * KST * 2u;

    float acc[2][4][4] = {};

    const int nkt = K >> 5;
    issue(0, 0);
    for (int j = 0; j < nkt; j++) {
        if (j + 1 < nkt) { issue((j + 1) & 1, (j + 1) << 5); CP_WAIT(1); }
        else             { CP_WAIT(0); }
        __syncthreads();
        const uint32_t sb = sbase + (uint32_t)((j & 1) * HG_STG) * 2u;
        const uint32_t aHiB = sb, aLoB = sb + 2560u * 2u;
        const uint32_t bHiB = sb + 5120u * 2u, bLoB = sb + 10240u * 2u;
        #pragma unroll
        for (int ks = 0; ks < 2; ks++) {
            const uint32_t kadd = (uint32_t)ks * 32u;
            uint32_t bh[2][4], bl[2][4], ah[2][4], al[2][4];
            ldsm4(bh[0][0], bh[0][1], bh[0][2], bh[0][3], bHiB + boff0 + kadd);
            ldsm4(bh[1][0], bh[1][1], bh[1][2], bh[1][3], bHiB + boff1 + kadd);
            ldsm4(bl[0][0], bl[0][1], bl[0][2], bl[0][3], bLoB + boff0 + kadd);
            ldsm4(bl[1][0], bl[1][1], bl[1][2], bl[1][3], bLoB + boff1 + kadd);
            ldsm4(ah[0][0], ah[0][1], ah[0][2], ah[0][3], aHiB + aoff0 + kadd);
            ldsm4(ah[1][0], ah[1][1], ah[1][2], ah[1][3], aHiB + aoff1 + kadd);
            ldsm4(al[0][0], al[0][1], al[0][2], al[0][3], aLoB + aoff0 + kadd);
            ldsm4(al[1][0], al[1][1], al[1][2], al[1][3], aLoB + aoff1 + kadd);
            #pragma unroll
            for (int mi = 0; mi < 2; mi++)
                #pragma unroll
                for (int ni = 0; ni < 4; ni++)
                    mma_f16(acc[mi][ni], ah[mi], &bh[ni >> 1][(ni & 1) * 2]);
            #pragma unroll
            for (int mi = 0; mi < 2; mi++)
                #pragma unroll
                for (int ni = 0; ni < 4; ni++)
                    mma_f16(acc[mi][ni], ah[mi], &bl[ni >> 1][(ni & 1) * 2]);
            #pragma unroll
            for (int mi = 0; mi < 2; mi++)
                #pragma unroll
                for (int ni = 0; ni < 4; ni++)
                    mma_f16(acc[mi][ni], al[mi], &bh[ni >> 1][(ni & 1) * 2]);
        }
        __syncthreads();
    }

    #pragma unroll
    for (int mi = 0; mi < 2; mi++) {
        #pragma unroll
        for (int half = 0; half < 2; half++) {
            const int row = m0 + wm * 32 + mi * 16 + gid + half * 8;
            if (GUARD && row >= cq) continue;
            #pragma unroll
            for (int ni = 0; ni < 4; ni++) {
                const int col = n0 + wn * 32 + ni * 8 + tig * 2;
                float vx = acc[mi][ni][half * 2 + 0] + bias[col];
                float vy = acc[mi][ni][half * 2 + 1] + bias[col + 1];
                if (EPI == 5) {
                    const float w = rw[row];
                    float* dst = C + (size_t)idx[row] * N + col;
                    atomicAdd(dst,     w * vx);
                    atomicAdd(dst + 1, w * vy);
                } else if (EPI == 6) {
                    vx = gelu1(vx); vy = gelu1(vy);
                    uint32_t hi, lo;
                    split2(vx, vy, hi, lo);
                    *(uint32_t*)&Ch[(size_t)row * N + col] = hi;
                    *(uint32_t*)&Cl[(size_t)row * N + col] = lo;
                } else {
                    float* dst = C + (size_t)row * N + col;
                    if (EPI == 3) {
                        const float2 cc = *(const float2*)dst;
                        vx += cc.x; vy += cc.y;
                    }
                    *(float2*)dst = make_float2(vx, vy);
                }
            }
        }
    }
}

// ---------------------------------------------------------------------------
// fp32-input GEMM (front-end only). EPI: 0 store, 1 gelu, 2 res+v.
// ---------------------------------------------------------------------------
#define AH_SZ (64 * KST)
#define BH_SZ (128 * KST)
#define OFF_AH(b) ((b) * AH_SZ)
#define OFF_AL(b) (2 * AH_SZ + (b) * AH_SZ)
#define OFF_BH(b) (4 * AH_SZ + (b) * BH_SZ)
#define OFF_BL(b) (4 * AH_SZ + 2 * BH_SZ + (b) * BH_SZ)
#define SMEM_MMA ((4 * AH_SZ + 4 * BH_SZ) * 2)

template<int EPI>
__global__ void __launch_bounds__(256, 2) mma_gemm(
    const float* __restrict__ A, const float* __restrict__ B,
    const float* __restrict__ bias, float* __restrict__ C,
    int M, int N, int K, const float* __restrict__ res)
{
    const int t = threadIdx.x, wid = t >> 5, lane = t & 31;
    const int m0 = blockIdx.y * 64, n0 = blockIdx.x * 128;

    extern __shared__ __half sh[];
    const uint32_t sbase = (uint32_t)__cvta_generic_to_shared(sh);

    const int arow = t >> 2, akof = (t & 3) * 8;
    const float* Agp = A + (size_t)(m0 + arow) * K + akof;
    const int nB = t & 127, kk2 = t >> 7;
    const float* Bcol = B + n0 + nB;

    const int wm = wid >> 2, wn = wid & 3;
    const int gid = lane >> 2, tig = lane & 3;
    const int l7 = lane & 7, q8 = lane >> 3;
    const int A_row = (q8 & 1) * 8 + l7, A_k = (q8 >> 1) * 8;
    const int B_row = (q8 >> 1) * 8 + l7, B_k = (q8 & 1) * 8;
    const uint32_t aoff0 = (uint32_t)((wm * 32 + A_row) * KST + A_k) * 2u;
    const uint32_t aoff1 = aoff0 + 16u * KST * 2u;
    const uint32_t boff0 = (uint32_t)((wn * 32 + B_row) * KST + B_k) * 2u;
    const uint32_t boff1 = boff0 + 16u * KST * 2u;

    float4 pa0, pa1;
    float pb[16];

    pa0 = *(const float4*)(Agp);
    pa1 = *(const float4*)(Agp + 4);
    #pragma unroll
    for (int i = 0; i < 4; i++)
        #pragma unroll
        for (int jj = 0; jj < 4; jj++)
            pb[i * 4 + jj] = Bcol[(size_t)(kk2 * 16 + i * 4 + jj) * N];
    {
        uint32_t h0,l0,h1,l1,h2,l2,h3,l3;
        split2(pa0.x, pa0.y, h0, l0); split2(pa0.z, pa0.w, h1, l1);
        split2(pa1.x, pa1.y, h2, l2); split2(pa1.z, pa1.w, h3, l3);
        *(uint4*)&sh[OFF_AH(0) + arow * KST + akof] = make_uint4(h0,h1,h2,h3);
        *(uint4*)&sh[OFF_AL(0) + arow * KST + akof] = make_uint4(l0,l1,l2,l3);
        #pragma unroll
        for (int i = 0; i < 4; i++) {
            const int kb = kk2 * 16 + i * 4;
            uint32_t bh0,bl0,bh1,bl1;
            split2(pb[i*4+0], pb[i*4+1], bh0, bl0);
            split2(pb[i*4+2], pb[i*4+3], bh1, bl1);
            *(uint2*)&sh[OFF_BH(0) + nB * KST + kb] = make_uint2(bh0, bh1);
            *(uint2*)&sh[OFF_BL(0) + nB * KST + kb] = make_uint2(bl0, bl1);
        }
    }
    __syncthreads();

    float acc[2][4][4] = {};

    const int nkt = K >> 5;
    for (int j = 0; j < nkt; j++) {
        const int cur = j & 1;
        const bool more = (j + 1 < nkt);
        if (more) {
            const int k0 = (j + 1) << 5;
            pa0 = *(const float4*)(Agp + k0);
            pa1 = *(const float4*)(Agp + k0 + 4);
            #pragma unroll
            for (int i = 0; i < 4; i++)
                #pragma unroll
                for (int jj = 0; jj < 4; jj++)
                    pb[i * 4 + jj] = Bcol[(size_t)(k0 + kk2 * 16 + i * 4 + jj) * N];
        }
        {
            const uint32_t aHiB = sbase + (uint32_t)OFF_AH(cur) * 2u;
            const uint32_t aLoB = sbase + (uint32_t)OFF_AL(cur) * 2u;
            const uint32_t bHiB = sbase + (uint32_t)OFF_BH(cur) * 2u;
            const uint32_t bLoB = sbase + (uint32_t)OFF_BL(cur) * 2u;
            #pragma unroll
            for (int ks = 0; ks < 2; ks++) {
                const uint32_t kadd = (uint32_t)ks * 32u;
                uint32_t bh[2][4], bl[2][4], ah[2][4], al[2][4];
                ldsm4(bh[0][0], bh[0][1], bh[0][2], bh[0][3], bHiB + boff0 + kadd);
                ldsm4(bh[1][0], bh[1][1], bh[1][2], bh[1][3], bHiB + boff1 + kadd);
                ldsm4(bl[0][0], bl[0][1], bl[0][2], bl[0][3], bLoB + boff0 + kadd);
                ldsm4(bl[1][0], bl[1][1], bl[1][2], bl[1][3], bLoB + boff1 + kadd);
                ldsm4(ah[0][0], ah[0][1], ah[0][2], ah[0][3], aHiB + aoff0 + kadd);
                ldsm4(ah[1][0], ah[1][1], ah[1][2], ah[1][3], aHiB + aoff1 + kadd);
                ldsm4(al[0][0], al[0][1], al[0][2], al[0][3], aLoB + aoff0 + kadd);
                ldsm4(al[1][0], al[1][1], al[1][2], al[1][3], aLoB + aoff1 + kadd);
                #pragma unroll
                for (int mi = 0; mi < 2; mi++)
                    #pragma unroll
                    for (int ni = 0; ni < 4; ni++)
                        mma_f16(acc[mi][ni], ah[mi], &bh[ni >> 1][(ni & 1) * 2]);
                #pragma unroll
                for (int mi = 0; mi < 2; mi++)
                    #pragma unroll
                    for (int ni = 0; ni < 4; ni++)
                        mma_f16(acc[mi][ni], ah[mi], &bl[ni >> 1][(ni & 1) * 2]);
                #pragma unroll
                for (int mi = 0; mi < 2; mi++)
                    #pragma unroll
                    for (int ni = 0; ni < 4; ni++)
                        mma_f16(acc[mi][ni], al[mi], &bh[ni >> 1][(ni & 1) * 2]);
            }
        }
        if (more) {
            const int nxt = cur ^ 1;
            uint32_t h0,l0,h1,l1,h2,l2,h3,l3;
            split2(pa0.x, pa0.y, h0, l0); split2(pa0.z, pa0.w, h1, l1);
            split2(pa1.x, pa1.y, h2, l2); split2(pa1.z, pa1.w, h3, l3);
            *(uint4*)&sh[OFF_AH(nxt) + arow * KST + akof] = make_uint4(h0,h1,h2,h3);
            *(uint4*)&sh[OFF_AL(nxt) + arow * KST + akof] = make_uint4(l0,l1,l2,l3);
            #pragma unroll
            for (int i = 0; i < 4; i++) {
                const int kb = kk2 * 16 + i * 4;
                uint32_t bh0,bl0,bh1,bl1;
                split2(pb[i*4+0], pb[i*4+1], bh0, bl0);
                split2(pb[i*4+2], pb[i*4+3], bh1, bl1);
                *(uint2*)&sh[OFF_BH(nxt) + nB * KST + kb] = make_uint2(bh0, bh1);
                *(uint2*)&sh[OFF_BL(nxt) + nB * KST + kb] = make_uint2(bl0, bl1);
            }
            __syncthreads();
        }
    }

    #pragma unroll
    for (int mi = 0; mi < 2; mi++) {
        #pragma unroll
        for (int half = 0; half < 2; half++) {
            const int row = m0 + wm * 32 + mi * 16 + gid + half * 8;
            #pragma unroll
            for (int ni = 0; ni < 4; ni++) {
                const int col = n0 + wn * 32 + ni * 8 + tig * 2;
                float vx = acc[mi][ni][half * 2 + 0] + bias[col];
                float vy = acc[mi][ni][half * 2 + 1] + bias[col + 1];
                float* dst = C + (size_t)row * N + col;
                if (EPI == 1) {
                    vx = gelu1(vx); vy = gelu1(vy);
                } else if (EPI == 2) {
                    const float2 rr = *(const float2*)(res + (size_t)row * N + col);
                    vx += rr.x; vy += rr.y;
                }
                *(float2*)dst = make_float2(vx, vy);
            }
        }
    }
}

// ---------------------------------------------------------------------------
// Flash attention: block per (b,head), thread per query row; writes HALVES.
// ---------------------------------------------------------------------------
#define KVP 68
#define SMEM_ATTN (2 * 128 * KVP * 4)

__global__ void __launch_bounds__(128) attn_flash(const float* __restrict__ qkv,
                                                  __half* __restrict__ oh,
                                                  __half* __restrict__ ol)
{
    const int bh = blockIdx.x;
    const int b = bh >> 3, hh = bh & 7;
    const int t = threadIdx.x;
    const float* base = qkv + (size_t)b * 128 * 1536 + hh * 64;

    extern __shared__ float kv[];
    float (*Ks)[KVP] = (float(*)[KVP])kv;
    float (*Vs)[KVP] = (float(*)[KVP])(kv + 128 * KVP);

    {
        const float* kr = base + (size_t)t * 1536 + 512;
        const float* vr = kr + 512;
        #pragma unroll
        for (int d4 = 0; d4 < 16; d4++) {
            *(float4*)&Ks[t][d4 * 4] = *(const float4*)(kr + d4 * 4);
            *(float4*)&Vs[t][d4 * 4] = *(const float4*)(vr + d4 * 4);
        }
    }
    float q[64];
    {
        const float* qr = base + (size_t)t * 1536;
        #pragma unroll
        for (int d4 = 0; d4 < 16; d4++) {
            float4 f = *(const float4*)(qr + d4 * 4);
            q[d4 * 4 + 0] = f.x; q[d4 * 4 + 1] = f.y;
            q[d4 * 4 + 2] = f.z; q[d4 * 4 + 3] = f.w;
        }
    }
    __syncthreads();

    float oacc[64];
    #pragma unroll
    for (int d = 0; d < 64; d++) oacc[d] = 0.f;
    float m = -1e30f, l = 0.f;

    for (int j = 0; j <= t; j++) {
        float s = 0.f;
        #pragma unroll
        for (int d4 = 0; d4 < 16; d4++) {
            float4 k4 = *(const float4*)&Ks[j][d4 * 4];
            s += q[d4 * 4 + 0] * k4.x + q[d4 * 4 + 1] * k4.y
               + q[d4 * 4 + 2] * k4.z + q[d4 * 4 + 3] * k4.w;
        }
        s *= 0.125f;
        const float nm = fmaxf(m, s);
        const float sc = __expf(m - nm), e = __expf(s - nm);
        l = l * sc + e;
        m = nm;
        #pragma unroll
        for (int d4 = 0; d4 < 16; d4++) {
            float4 v4 = *(const float4*)&Vs[j][d4 * 4];
            oacc[d4 * 4 + 0] = oacc[d4 * 4 + 0] * sc + e * v4.x;
            oacc[d4 * 4 + 1] = oacc[d4 * 4 + 1] * sc + e * v4.y;
            oacc[d4 * 4 + 2] = oacc[d4 * 4 + 2] * sc + e * v4.z;
            oacc[d4 * 4 + 3] = oacc[d4 * 4 + 3] * sc + e * v4.w;
        }
    }
    const float inv = 1.0f / l;
    const size_t oo = ((size_t)b * 128 + t) * 512 + hh * 64;
    #pragma unroll
    for (int d4 = 0; d4 < 16; d4++) {
        uint32_t h0, l0, h1, l1;
        split2(oacc[d4 * 4 + 0] * inv, oacc[d4 * 4 + 1] * inv, h0, l0);
        split2(oacc[d4 * 4 + 2] * inv, oacc[d4 * 4 + 3] * inv, h1, l1);
        *(uint2*)&oh[oo + d4 * 4] = make_uint2(h0, h1);
        *(uint2*)&ol[oo + d4 * 4] = make_uint2(l0, l1);
    }
}

// ---------------------------------------------------------------------------
__global__ void patchnorm_kernel(const float* __restrict__ x, float* __restrict__ y)
{
    const int warp = threadIdx.x >> 5, lane = threadIdx.x & 31;
    const int row = blockIdx.x * 8 + warp;
    const float* xr = x + (size_t)row * 128;
    float4 f = *(const float4*)(xr + lane * 4);
    float s = f.x + f.y + f.z + f.w;
    #pragma unroll
    for (int o = 16; o; o >>= 1) s += __shfl_xor_sync(0xffffffffu, s, o);
    const float mu = s * (1.0f / 128.0f);
    float q = (f.x - mu) * (f.x - mu) + (f.y - mu) * (f.y - mu)
            + (f.z - mu) * (f.z - mu) + (f.w - mu) * (f.w - mu);
    #pragma unroll
    for (int o = 16; o; o >>= 1) q += __shfl_xor_sync(0xffffffffu, q, o);
    const float rs = rsqrtf(q * (1.0f / 128.0f) + 1e-6f);
    float4 r = make_float4((f.x - mu) * rs, (f.y - mu) * rs, (f.z - mu) * rs, (f.w - mu) * rs);
    *(float4*)(y + (size_t)row * 128 + lane * 4) = r;
}

// LayerNorm over 512; writes fp32 y AND half hi/lo yh/yl.
__global__ void ln512d_kernel(const float* __restrict__ x, float* __restrict__ y,
                              __half* __restrict__ yh, __half* __restrict__ yl,
                              const float* __restrict__ g, const float* __restrict__ b)
{
    const int warp = threadIdx.x >> 5, lane = threadIdx.x & 31;
    const int row = blockIdx.x * 8 + warp;
    const float* xr = x + (size_t)row * 512;
    float v[16];
    float s = 0.f;
    #pragma unroll
    for (int c = 0; c < 4; c++) {
        float4 f = *(const float4*)(xr + c * 128 + lane * 4);
        v[c * 4 + 0] = f.x; v[c * 4 + 1] = f.y; v[c * 4 + 2] = f.z; v[c * 4 + 3] = f.w;
        s += f.x + f.y + f.z + f.w;
    }
    #pragma unroll
    for (int o = 16; o; o >>= 1) s += __shfl_xor_sync(0xffffffffu, s, o);
    const float mu = s * (1.0f / 512.0f);
    float q = 0.f;
    #pragma unroll
    for (int k = 0; k < 16; k++) { float d = v[k] - mu; q += d * d; }
    #pragma unroll
    for (int o = 16; o; o >>= 1) q += __shfl_xor_sync(0xffffffffu, q, o);
    const float rs = rsqrtf(q * (1.0f / 512.0f) + 1e-5f);
    #pragma unroll
    for (int c = 0; c < 4; c++) {
        const int col = c * 128 + lane * 4;
        float4 gg = *(const float4*)(g + col);
        float4 bb = *(const float4*)(b + col);
        float4 r;
        r.x = gg.x * (v[c * 4 + 0] - mu) * rs + bb.x;
        r.y = gg.y * (v[c * 4 + 1] - mu) * rs + bb.y;
        r.z = gg.z * (v[c * 4 + 2] - mu) * rs + bb.z;
        r.w = gg.w * (v[c * 4 + 3] - mu) * rs + bb.w;
        *(float4*)(y + (size_t)row * 512 + col) = r;
        uint32_t h0, l0, h1, l1;
        split2(r.x, r.y, h0, l0);
        split2(r.z, r.w, h1, l1);
        *(uint2*)&yh[(size_t)row * 512 + col] = make_uint2(h0, h1);
        *(uint2*)&yl[(size_t)row * 512 + col] = make_uint2(l0, l1);
    }
}

__global__ void freqadd_kernel(float* __restrict__ h, const float* __restrict__ emb,
                               const int* __restrict__ fid)
{
    const int i = blockIdx.x * 256 + threadIdx.x;
    const int row = i >> 9, d = i & 511, b = row >> 7;
    h[i] += emb[(size_t)fid[b] * 512 + d];
}

__global__ void zero_cnt_kernel(int* cnt)
{
    if (threadIdx.x < 4) cnt[threadIdx.x] = 0;
}

__global__ void gate_route_kernel(const float* __restrict__ hn, const float* __restrict__ gw,
                                  const float* __restrict__ gb,
                                  int* __restrict__ cnt, int* __restrict__ idx,
                                  float* __restrict__ rw)
{
    const int warp = threadIdx.x >> 5, lane = threadIdx.x & 31;
    const int row = blockIdx.x * 8 + warp;
    const float* xr = hn + (size_t)row * 512;
    float a0 = 0.f, a1 = 0.f, a2 = 0.f, a3 = 0.f;
    for (int d = lane; d < 512; d += 32) {
        const float hv = xr[d];
        float4 w = *(const float4*)(gw + (size_t)d * 4);
        a0 += hv * w.x; a1 += hv * w.y; a2 += hv * w.z; a3 += hv * w.w;
    }
    #pragma unroll
    for (int o = 16; o; o >>= 1) {
        a0 += __shfl_xor_sync(0xffffffffu, a0, o);
        a1 += __shfl_xor_sync(0xffffffffu, a1, o);
        a2 += __shfl_xor_sync(0xffffffffu, a2, o);
        a3 += __shfl_xor_sync(0xffffffffu, a3, o);
    }
    if (lane == 0) {
        float p[4] = {a0 + gb[0], a1 + gb[1], a2 + gb[2], a3 + gb[3]};
        const float mx = fmaxf(fmaxf(p[0], p[1]), fmaxf(p[2], p[3]));
        float s = 0.f;
        #pragma unroll
        for (int e = 0; e < 4; e++) { p[e] = expf(p[e] - mx); s += p[e]; }
        const float invs = 1.0f / s;
        #pragma unroll
        for (int e = 0; e < 4; e++) p[e] *= invs;
        int i0 = 0;
        #pragma unroll
        for (int e = 1; e < 4; e++) if (p[e] > p[i0]) i0 = e;
        int i1 = -1;
        #pragma unroll
        for (int e = 0; e < 4; e++) if (e != i0 && (i1 < 0 || p[e] > p[i1])) i1 = e;
        int s0 = atomicAdd(&cnt[i0], 1);
        idx[i0 * T_TOK + s0] = row; rw[i0 * T_TOK + s0] = p[i0];
        int s1 = atomicAdd(&cnt[i1], 1);
        idx[i1 * T_TOK + s1] = row; rw[i1 * T_TOK + s1] = p[i1];
    }
}

__global__ void head_kernel(const float* __restrict__ h,
                            const float* __restrict__ fng, const float* __restrict__ fnb,
                            const float* __restrict__ hg,  const float* __restrict__ hb,
                            const float* __restrict__ hw,  const float* __restrict__ hbias,
                            float* __restrict__ out, int out_size)
{
    const int warp = threadIdx.x >> 5, lane = threadIdx.x & 31;
    const int b = warp;
    const float* xr = h + ((size_t)b * 128 + 127) * 512;
    float v[16];
    float s = 0.f;
    #pragma unroll
    for (int c = 0; c < 4; c++) {
        float4 f = *(const float4*)(xr + c * 128 + lane * 4);
        v[c * 4 + 0] = f.x; v[c * 4 + 1] = f.y; v[c * 4 + 2] = f.z; v[c * 4 + 3] = f.w;
        s += f.x + f.y + f.z + f.w;
    }
    #pragma unroll
    for (int o = 16; o; o >>= 1) s += __shfl_xor_sync(0xffffffffu, s, o);
    float mu = s * (1.0f / 512.0f);
    float q = 0.f;
    #pragma unroll
    for (int k = 0; k < 16; k++) { float d = v[k] - mu; q += d * d; }
    #pragma unroll
    for (int o = 16; o; o >>= 1) q += __shfl_xor_sync(0xffffffffu, q, o);
    float rs = rsqrtf(q * (1.0f / 512.0f) + 1e-5f);
    #pragma unroll
    for (int c = 0; c < 4; c++)
        #pragma unroll
        for (int j = 0; j < 4; j++) {
            const int col = c * 128 + lane * 4 + j;
            v[c * 4 + j] = fng[col] * (v[c * 4 + j] - mu) * rs + fnb[col];
        }
    s = 0.f;
    #pragma unroll
    for (int k = 0; k < 16; k++) s += v[k];
    #pragma unroll
    for (int o = 16; o; o >>= 1) s += __shfl_xor_sync(0xffffffffu, s, o);
    mu = s * (1.0f / 512.0f);
    q = 0.f;
    #pragma unroll
    for (int k = 0; k < 16; k++) { float d = v[k] - mu; q += d * d; }
    #pragma unroll
    for (int o = 16; o; o >>= 1) q += __shfl_xor_sync(0xffffffffu, q, o);
    rs = rsqrtf(q * (1.0f / 512.0f) + 1e-5f);
    float dot = 0.f;
    #pragma unroll
    for (int c = 0; c < 4; c++)
        #pragma unroll
        for (int j = 0; j < 4; j++) {
            const int col = c * 128 + lane * 4 + j;
            const float hl = hg[col] * (v[c * 4 + j] - mu) * rs + hb[col];
            dot += hl * hw[col];
        }
    #pragma unroll
    for (int o = 16; o; o >>= 1) dot += __shfl_xor_sync(0xffffffffu, dot, o);
    if (lane == 0) {
        const float logit = dot + hbias[0];
        if (out_size >= 32) {
            out[b] = logit;
            out[16 + b] = 1.0f / (1.0f + expf(-logit));
        } else {
            out[b] = logit;
        }
    }
}

// ---------------------------------------------------------------------------
extern "C" void kernel_launch(void* const* d_in, const int* in_sizes, int n_in,
                              void* d_out, int out_size)
{
    const float* x        = (const float*)d_in[0];
    const int*   fid      = (const int*)  d_in[1];
    const float* ir_w1    = (const float*)d_in[2];
    const float* ir_b1    = (const float*)d_in[3];
    const float* ir_w2    = (const float*)d_in[4];
    const float* ir_b2    = (const float*)d_in[5];
    const float* p2m_w    = (const float*)d_in[6];
    const float* p2m_b    = (const float*)d_in[7];
    const float* freq_emb = (const float*)d_in[8];
    const float* ln1_g    = (const float*)d_in[9];
    const float* ln1_b    = (const float*)d_in[10];
    const float* qkv_w    = (const float*)d_in[11];
    const float* qkv_b    = (const float*)d_in[12];
    const float* out_w    = (const float*)d_in[13];
    const float* out_b    = (const float*)d_in[14];
    const float* ln2_g    = (const float*)d_in[15];
    const float* ln2_b    = (const float*)d_in[16];
    const float* gate_w   = (const float*)d_in[17];
    const float* gate_b   = (const float*)d_in[18];
    const float* exp_w1   = (const float*)d_in[19];
    const float* exp_b1   = (const float*)d_in[20];
    const float* exp_w2   = (const float*)d_in[21];
    const float* exp_b2   = (const float*)d_in[22];
    const float* fn_g     = (const float*)d_in[23];
    const float* fn_b     = (const float*)d_in[24];
    const float* head_g   = (const float*)d_in[25];
    const float* head_b   = (const float*)d_in[26];
    const float* head_w   = (const float*)d_in[27];
    const float* head_bias= (const float*)d_in[28];

    float *patches, *tmp, *hp, *h, *hn, *qkv, *rw;
    int *cnt, *idx;
    __half *qkvTh, *qkvTl, *outTh, *outTl, *e1Th, *e1Tl, *e2Th, *e2Tl;
    __half *hnh, *hnl, *ath, *atl, *ehh, *ehl;
    cudaGetSymbolAddress((void**)&patches, g_patches);
    cudaGetSymbolAddress((void**)&tmp,     g_tmp);
    cudaGetSymbolAddress((void**)&hp,      g_hp);
    cudaGetSymbolAddress((void**)&h,       g_h);
    cudaGetSymbolAddress((void**)&hn,      g_hn);
    cudaGetSymbolAddress((void**)&qkv,     g_qkv);
    cudaGetSymbolAddress((void**)&cnt,     g_cnt);
    cudaGetSymbolAddress((void**)&idx,     g_idx);
    cudaGetSymbolAddress((void**)&rw,      g_rw);
    cudaGetSymbolAddress((void**)&qkvTh,   g_qkvTh);
    cudaGetSymbolAddress((void**)&qkvTl,   g_qkvTl);
    cudaGetSymbolAddress((void**)&outTh,   g_outTh);
    cudaGetSymbolAddress((void**)&outTl,   g_outTl);
    cudaGetSymbolAddress((void**)&e1Th,    g_e1Th);
    cudaGetSymbolAddress((void**)&e1Tl,    g_e1Tl);
    cudaGetSymbolAddress((void**)&e2Th,    g_e2Th);
    cudaGetSymbolAddress((void**)&e2Tl,    g_e2Tl);
    cudaGetSymbolAddress((void**)&hnh,     g_hnh);
    cudaGetSymbolAddress((void**)&hnl,     g_hnl);
    cudaGetSymbolAddress((void**)&ath,     g_ath);
    cudaGetSymbolAddress((void**)&atl,     g_atl);
    cudaGetSymbolAddress((void**)&ehh,     g_ehh);
    cudaGetSymbolAddress((void**)&ehl,     g_ehl);

    cudaFuncSetAttribute(mma_gemm<0>, cudaFuncAttributeMaxDynamicSharedMemorySize, SMEM_MMA);
    cudaFuncSetAttribute(mma_gemm<1>, cudaFuncAttributeMaxDynamicSharedMemorySize, SMEM_MMA);
    cudaFuncSetAttribute(mma_gemm<2>, cudaFuncAttributeMaxDynamicSharedMemorySize, SMEM_MMA);
    cudaFuncSetAttribute(hgemm<0,false,false,false>, cudaFuncAttributeMaxDynamicSharedMemorySize, SMEM_HG);
    cudaFuncSetAttribute(hgemm<3,false,false,false>, cudaFuncAttributeMaxDynamicSharedMemorySize, SMEM_HG);
    cudaFuncSetAttribute(hgemm<6,true,true,true>,    cudaFuncAttributeMaxDynamicSharedMemorySize, SMEM_HG);
    cudaFuncSetAttribute(hgemm<5,false,true,true>,   cudaFuncAttributeMaxDynamicSharedMemorySize, SMEM_HG);
    cudaFuncSetAttribute(attn_flash, cudaFuncAttributeMaxDynamicSharedMemorySize, SMEM_ATTN);

    // ---- pre-split all weights (hi/lo halves, transposed [N][K]) ----
    wsplitT<<<dim3(24, 16, 12), 256>>>(qkv_w,  qkvTh, qkvTl, 512, 1536);
    wsplitT<<<dim3(8,  16, 12), 256>>>(out_w,  outTh, outTl, 512, 512);
    wsplitT<<<dim3(32, 16, 48), 256>>>(exp_w1, e1Th,  e1Tl,  512, 2048);
    wsplitT<<<dim3(8,  64, 48), 256>>>(exp_w2, e2Th,  e2Tl,  2048, 512);

    // ---- front end (fp32 path) ----
    patchnorm_kernel<<<256, 256>>>(x, patches);
    mma_gemm<1><<<dim3(4, 32), 256, SMEM_MMA>>>(patches, ir_w1, ir_b1, tmp,
        T_TOK, 512, 128, nullptr);
    mma_gemm<2><<<dim3(1, 32), 256, SMEM_MMA>>>(tmp, ir_w2, ir_b2, hp,
        T_TOK, 128, 512, patches);
    mma_gemm<0><<<dim3(4, 32), 256, SMEM_MMA>>>(hp, p2m_w, p2m_b, h,
        T_TOK, 512, 128, nullptr);
    freqadd_kernel<<<(T_TOK * 512) / 256, 256>>>(h, freq_emb, fid);

    const size_t EHZ = (size_t)T_TOK * HDIM;

    for (int l = 0; l < 12; l++) {
        // attention
        ln512d_kernel<<<256, 256>>>(h, hn, hnh, hnl,
                                    ln1_g + (size_t)l * 512, ln1_b + (size_t)l * 512);
        hgemm<0,false,false,false><<<dim3(12, 32), 256, SMEM_HG>>>(
            hnh, hnl, qkvTh + (size_t)l * 1536 * 512, qkvTl + (size_t)l * 1536 * 512,
            qkv_b + (size_t)l * 1536, qkv, nullptr, nullptr,
            T_TOK, 1536, 512, nullptr, nullptr, nullptr, 0, 0);
        attn_flash<<<128, 128, SMEM_ATTN>>>(qkv, ath, atl);
        hgemm<3,false,false,false><<<dim3(4, 32), 256, SMEM_HG>>>(
            ath, atl, outTh + (size_t)l * 512 * 512, outTl + (size_t)l * 512 * 512,
            out_b + (size_t)l * 512, h, nullptr, nullptr,
            T_TOK, 512, 512, nullptr, nullptr, nullptr, 0, 0);
        // sparse MoE
        ln512d_kernel<<<256, 256>>>(h, hn, hnh, hnl,
                                    ln2_g + (size_t)l * 512, ln2_b + (size_t)l * 512);
        zero_cnt_kernel<<<1, 32>>>(cnt);
        gate_route_kernel<<<256, 256>>>(hn, gate_w + (size_t)l * 512 * 4,
                                        gate_b + (size_t)l * 4, cnt, idx, rw);
        hgemm<6,true,true,true><<<dim3(16, 32, 4), 256, SMEM_HG>>>(
            hnh, hnl, e1Th + (size_t)l * 4 * 2048 * 512, e1Tl + (size_t)l * 4 * 2048 * 512,
            exp_b1 + (size_t)l * 4 * 2048, nullptr, ehh, ehl,
            T_TOK, 2048, 512, idx, nullptr, cnt, 0, EHZ);
        hgemm<5,false,true,true><<<dim3(4, 32, 4), 256, SMEM_HG>>>(
            ehh, ehl, e2Th + (size_t)l * 4 * 512 * 2048, e2Tl + (size_t)l * 4 * 512 * 2048,
            exp_b2 + (size_t)l * 4 * 512, h, nullptr, nullptr,
            T_TOK, 512, 2048, idx, rw, cnt, EHZ, 0);
    }

    head_kernel<<<1, 512>>>(h, fn_g, fn_b, head_g, head_b, head_w, head_bias,
                            (float*)d_out, out_size);
}

// round 15
// speedup vs baseline: 1.0699x; 1.0206x over previous
#include <cuda_runtime.h>
#include <cuda_fp16.h>
#include <math.h>
#include <stdint.h>

// ---------------------------------------------------------------------------
// B=16, S=2048, C=8, P=16 -> N=128 patches, T=2048 tokens
// PD=128, IRH=512, D=512, NH=8, dh=64, L=12, E=4, H=2048, top-2 routing
// Split-precision fp16 HMMA GEMMs, pre-split hi/lo operands, fused LN+gate,
// split-K out-projection.
// ---------------------------------------------------------------------------
#define T_TOK 2048
#define DIM   512
#define HDIM  2048

__device__ float g_patches[T_TOK * 128];
__device__ float g_tmp    [T_TOK * 512];
__device__ float g_hp     [T_TOK * 128];
__device__ float g_h      [T_TOK * DIM];
__device__ float g_qkv    [T_TOK * 3 * DIM];
__device__ int   g_cnt    [4];
__device__ int   g_idx    [4 * T_TOK];
__device__ float g_rw     [4 * T_TOK];

__device__ __half g_qkvTh[12 * 1536 * 512];
__device__ __half g_qkvTl[12 * 1536 * 512];
__device__ __half g_outTh[12 * 512 * 512];
__device__ __half g_outTl[12 * 512 * 512];
__device__ __half g_e1Th [48 * 2048 * 512];
__device__ __half g_e1Tl [48 * 2048 * 512];
__device__ __half g_e2Th [48 * 512 * 2048];
__device__ __half g_e2Tl [48 * 512 * 2048];
__device__ __half g_hnh  [T_TOK * 512];
__device__ __half g_hnl  [T_TOK * 512];
__device__ __half g_ath  [T_TOK * 512];
__device__ __half g_atl  [T_TOK * 512];
__device__ __half g_ehh  [4 * T_TOK * 2048];
__device__ __half g_ehl  [4 * T_TOK * 2048];

// ---- helpers ---------------------------------------------------------------
__device__ __forceinline__ void split2(float f0, float f1, uint32_t& hi, uint32_t& lo) {
    __half2 h = __floats2half2_rn(f0, f1);
    float2 hf = __half22float2(h);
    __half2 l = __floats2half2_rn(f0 - hf.x, f1 - hf.y);
    hi = *(uint32_t*)&h;
    lo = *(uint32_t*)&l;
}
__device__ __forceinline__ void mma_f16(float* d, const uint32_t* a, const uint32_t* b) {
    asm volatile(
        "mma.sync.aligned.m16n8k16.row.col.f32.f16.f16.f32 "
        "{%0,%1,%2,%3}, {%4,%5,%6,%7}, {%8,%9}, {%0,%1,%2,%3};"
        : "+f"(d[0]), "+f"(d[1]), "+f"(d[2]), "+f"(d[3])
        : "r"(a[0]), "r"(a[1]), "r"(a[2]), "r"(a[3]), "r"(b[0]), "r"(b[1]));
}
__device__ __forceinline__ void ldsm4(uint32_t& r0, uint32_t& r1, uint32_t& r2,
                                      uint32_t& r3, uint32_t addr) {
    asm volatile("ldmatrix.sync.aligned.m8n8.x4.shared.b16 {%0,%1,%2,%3}, [%4];"
                 : "=r"(r0), "=r"(r1), "=r"(r2), "=r"(r3) : "r"(addr));
}
__device__ __forceinline__ void cpasync16(uint32_t s, const void* g) {
    asm volatile("cp.async.ca.shared.global [%0], [%1], 16;" :: "r"(s), "l"(g));
}
#define CP_COMMIT() asm volatile("cp.async.commit_group;" ::: "memory")
#define CP_WAIT(n)  asm volatile("cp.async.wait_group %0;" :: "n"(n) : "memory")

__device__ __forceinline__ float gelu1(float v) {
    return 0.5f * v * (1.0f + erff(v * 0.70710678118654752f));
}

// ---------------------------------------------------------------------------
// Weight split + transpose: w [K][N] fp32 -> whi/wlo [N][K] halves.
// ---------------------------------------------------------------------------
__global__ void __launch_bounds__(256) wsplitT(const float* __restrict__ w,
        __half* __restrict__ whi, __half* __restrict__ wlo, int K, int N)
{
    const size_t zoff = (size_t)blockIdx.z * K * N;
    w += zoff; whi += zoff; wlo += zoff;
    const int n0 = blockIdx.x * 64, k0 = blockIdx.y * 32;
    __shared__ float tile[32][65];
    const int t = threadIdx.x;
    #pragma unroll
    for (int i = 0; i < 8; i++) {
        const int e = t + i * 256;
        const int k = e >> 6, n = e & 63;
        tile[k][n] = w[(size_t)(k0 + k) * N + n0 + n];
    }
    __syncthreads();
    const int n = t >> 2, c = (t & 3) * 8;
    uint32_t hi[4], lo[4];
    #pragma unroll
    for (int i = 0; i < 4; i++)
        split2(tile[c + 2 * i][n], tile[c + 2 * i + 1][n], hi[i], lo[i]);
    const size_t o = (size_t)(n0 + n) * K + k0 + c;
    *(uint4*)&whi[o] = make_uint4(hi[0], hi[1], hi[2], hi[3]);
    *(uint4*)&wlo[o] = make_uint4(lo[0], lo[1], lo[2], lo[3]);
}

// ---------------------------------------------------------------------------
// hgemm: pre-split halves, 64x128 tile, BK=32, 2-stage cp.async.
// EPI: 0 store fp32, 5 atomic scatter, 6 gelu->half hi/lo, 7 atomicAdd (+bias z0)
// SK: split-K count (blockIdx.z = k slice when SK>1; EXPZ must be false)
// ---------------------------------------------------------------------------
#define KST 40
#define HG_STG 15360
#define SMEM_HG (2 * HG_STG * 2)

template<int EPI, bool GA, bool GUARD, bool EXPZ, int SK>
__global__ void __launch_bounds__(256, 2) hgemm(
    const __half* __restrict__ Ah, const __half* __restrict__ Al,
    const __half* __restrict__ Bh, const __half* __restrict__ Bl,
    const float* __restrict__ bias,
    float* __restrict__ C, __half* __restrict__ Ch, __half* __restrict__ Cl,
    int M, int N, int K,
    const int* __restrict__ idx, const float* __restrict__ rw,
    const int* __restrict__ cnt, size_t zA, size_t zC)
{
    if (EXPZ) {
        const int z = blockIdx.z;
        Ah += (size_t)z * zA; Al += (size_t)z * zA;
        Bh += (size_t)z * (size_t)K * N; Bl += (size_t)z * (size_t)K * N;
        bias += (size_t)z * N;
        if (EPI == 6) { Ch += (size_t)z * zC; Cl += (size_t)z * zC; }
        else          { C  += (size_t)z * zC; }
        idx += z * T_TOK;
        if (rw) rw += z * T_TOK;
        cnt += z;
    }
    int koff = 0;
    float bsc = 1.f;
    if (SK > 1) {
        koff = blockIdx.z * (K / SK);
        if (blockIdx.z != 0) bsc = 0.f;
    }
    const int klen = (SK > 1) ? (K / SK) : K;

    const int t = threadIdx.x, wid = t >> 5, lane = t & 31;
    const int m0 = blockIdx.y * 64, n0 = blockIdx.x * 128;

    int cq = M;
    if (GUARD) { cq = *cnt; if (m0 >= cq) return; }

    extern __shared__ __half sh[];
    const uint32_t sbase = (uint32_t)__cvta_generic_to_shared(sh);

    const int arow = t >> 2, acof = (t & 3) * 8;
    int garow = m0 + arow;
    if (GA) garow = (garow < cq) ? idx[garow] : idx[0];
    const __half* Asrc_h = Ah + (size_t)garow * K + koff + acof;
    const __half* Asrc_l = Al + (size_t)garow * K + koff + acof;
    const int brow = t >> 1;
    const int bcof0 = ((2 * t) & 3) * 8, bcof1 = ((2 * t + 1) & 3) * 8;
    const __half* Bsrc_h = Bh + (size_t)(n0 + brow) * K + koff;
    const __half* Bsrc_l = Bl + (size_t)(n0 + brow) * K + koff;

    const uint32_t adst  = (uint32_t)(arow * KST + acof) * 2u;
    const uint32_t bdst0 = (uint32_t)(brow * KST + bcof0) * 2u;
    const uint32_t bdst1 = (uint32_t)(brow * KST + bcof1) * 2u;

    auto issue = [&](int s, int k0) {
        const uint32_t sb = sbase + (uint32_t)(s * HG_STG) * 2u;
        cpasync16(sb + adst,               Asrc_h + k0);
        cpasync16(sb + 2560u * 2u + adst,  Asrc_l + k0);
        cpasync16(sb + 5120u * 2u + bdst0, Bsrc_h + k0 + bcof0);
        cpasync16(sb + 5120u * 2u + bdst1, Bsrc_h + k0 + bcof1);
        cpasync16(sb + 10240u * 2u + bdst0, Bsrc_l + k0 + bcof0);
        cpasync16(sb + 10240u * 2u + bdst1, Bsrc_l + k0 + bcof1);
        CP_COMMIT();
    };

    const int wm = wid >> 2, wn = wid & 3;
    const int gid = lane >> 2, tig = lane & 3;
    const int l7 = lane & 7, q8 = lane >> 3;
    const int A_row = (q8 & 1) * 8 + l7, A_k = (q8 >> 1) * 8;
    const int B_row = (q8 >> 1) * 8 + l7, B_k = (q8 & 1) * 8;
    const uint32_t aoff0 = (uint32_t)((wm * 32 + A_row) * KST + A_k) * 2u;
    const uint32_t aoff1 = aoff0 + 16u * KST * 2u;
    const uint32_t boff0 = (uint32_t)((wn * 32 + B_row) * KST + B_k) * 2u;
    const uint32_t boff1 = boff0 + 16u * KST * 2u;

    float acc[2][4][4] = {};

    const int nkt = klen >> 5;
    issue(0, 0);
    for (int j = 0; j < nkt; j++) {
        if (j + 1 < nkt) { issue((j + 1) & 1, (j + 1) << 5); CP_WAIT(1); }
        else             { CP_WAIT(0); }
        __syncthreads();
        const uint32_t sb = sbase + (uint32_t)((j & 1) * HG_STG) * 2u;
        const uint32_t aHiB = sb, aLoB = sb + 2560u * 2u;
        const uint32_t bHiB = sb + 5120u * 2u, bLoB = sb + 10240u * 2u;
        #pragma unroll
        for (int ks = 0; ks < 2; ks++) {
            const uint32_t kadd = (uint32_t)ks * 32u;
            uint32_t bh[2][4], bl[2][4], ah[2][4], al[2][4];
            ldsm4(bh[0][0], bh[0][1], bh[0][2], bh[0][3], bHiB + boff0 + kadd);
            ldsm4(bh[1][0], bh[1][1], bh[1][2], bh[1][3], bHiB + boff1 + kadd);
            ldsm4(bl[0][0], bl[0][1], bl[0][2], bl[0][3], bLoB + boff0 + kadd);
            ldsm4(bl[1][0], bl[1][1], bl[1][2], bl[1][3], bLoB + boff1 + kadd);
            ldsm4(ah[0][0], ah[0][1], ah[0][2], ah[0][3], aHiB + aoff0 + kadd);
            ldsm4(ah[1][0], ah[1][1], ah[1][2], ah[1][3], aHiB + aoff1 + kadd);
            ldsm4(al[0][0], al[0][1], al[0][2], al[0][3], aLoB + aoff0 + kadd);
            ldsm4(al[1][0], al[1][1], al[1][2], al[1][3], aLoB + aoff1 + kadd);
            #pragma unroll
            for (int mi = 0; mi < 2; mi++)
                #pragma unroll
                for (int ni = 0; ni < 4; ni++)
                    mma_f16(acc[mi][ni], ah[mi], &bh[ni >> 1][(ni & 1) * 2]);
            #pragma unroll
            for (int mi = 0; mi < 2; mi++)
                #pragma unroll
                for (int ni = 0; ni < 4; ni++)
                    mma_f16(acc[mi][ni], ah[mi], &bl[ni >> 1][(ni & 1) * 2]);
            #pragma unroll
            for (int mi = 0; mi < 2; mi++)
                #pragma unroll
                for (int ni = 0; ni < 4; ni++)
                    mma_f16(acc[mi][ni], al[mi], &bh[ni >> 1][(ni & 1) * 2]);
        }
        __syncthreads();
    }

    #pragma unroll
    for (int mi = 0; mi < 2; mi++) {
        #pragma unroll
        for (int half = 0; half < 2; half++) {
            const int row = m0 + wm * 32 + mi * 16 + gid + half * 8;
            if (GUARD && row >= cq) continue;
            #pragma unroll
            for (int ni = 0; ni < 4; ni++) {
                const int col = n0 + wn * 32 + ni * 8 + tig * 2;
                if (EPI == 7) {
                    float* dst = C + (size_t)row * N + col;
                    atomicAdd(dst,     acc[mi][ni][half * 2 + 0] + bsc * bias[col]);
                    atomicAdd(dst + 1, acc[mi][ni][half * 2 + 1] + bsc * bias[col + 1]);
                    continue;
                }
                float vx = acc[mi][ni][half * 2 + 0] + bias[col];
                float vy = acc[mi][ni][half * 2 + 1] + bias[col + 1];
                if (EPI == 5) {
                    const float w = rw[row];
                    float* dst = C + (size_t)idx[row] * N + col;
                    atomicAdd(dst,     w * vx);
                    atomicAdd(dst + 1, w * vy);
                } else if (EPI == 6) {
                    vx = gelu1(vx); vy = gelu1(vy);
                    uint32_t hi, lo;
                    split2(vx, vy, hi, lo);
                    *(uint32_t*)&Ch[(size_t)row * N + col] = hi;
                    *(uint32_t*)&Cl[(size_t)row * N + col] = lo;
                } else {
                    *(float2*)(C + (size_t)row * N + col) = make_float2(vx, vy);
                }
            }
        }
    }
}

// ---------------------------------------------------------------------------
// fp32-input GEMM (front-end only). EPI: 0 store, 1 gelu, 2 res+v.
// ---------------------------------------------------------------------------
#define AH_SZ (64 * KST)
#define BH_SZ (128 * KST)
#define OFF_AH(b) ((b) * AH_SZ)
#define OFF_AL(b) (2 * AH_SZ + (b) * AH_SZ)
#define OFF_BH(b) (4 * AH_SZ + (b) * BH_SZ)
#define OFF_BL(b) (4 * AH_SZ + 2 * BH_SZ + (b) * BH_SZ)
#define SMEM_MMA ((4 * AH_SZ + 4 * BH_SZ) * 2)

template<int EPI>
__global__ void __launch_bounds__(256, 2) mma_gemm(
    const float* __restrict__ A, const float* __restrict__ B,
    const float* __restrict__ bias, float* __restrict__ C,
    int M, int N, int K, const float* __restrict__ res)
{
    const int t = threadIdx.x, wid = t >> 5, lane = t & 31;
    const int m0 = blockIdx.y * 64, n0 = blockIdx.x * 128;

    extern __shared__ __half sh[];
    const uint32_t sbase = (uint32_t)__cvta_generic_to_shared(sh);

    const int arow = t >> 2, akof = (t & 3) * 8;
    const float* Agp = A + (size_t)(m0 + arow) * K + akof;
    const int nB = t & 127, kk2 = t >> 7;
    const float* Bcol = B + n0 + nB;

    const int wm = wid >> 2, wn = wid & 3;
    const int gid = lane >> 2, tig = lane & 3;
    const int l7 = lane & 7, q8 = lane >> 3;
    const int A_row = (q8 & 1) * 8 + l7, A_k = (q8 >> 1) * 8;
    const int B_row = (q8 >> 1) * 8 + l7, B_k = (q8 & 1) * 8;
    const uint32_t aoff0 = (uint32_t)((wm * 32 + A_row) * KST + A_k) * 2u;
    const uint32_t aoff1 = aoff0 + 16u * KST * 2u;
    const uint32_t boff0 = (uint32_t)((wn * 32 + B_row) * KST + B_k) * 2u;
    const uint32_t boff1 = boff0 + 16u * KST * 2u;

    float4 pa0, pa1;
    float pb[16];

    pa0 = *(const float4*)(Agp);
    pa1 = *(const float4*)(Agp + 4);
    #pragma unroll
    for (int i = 0; i < 4; i++)
        #pragma unroll
        for (int jj = 0; jj < 4; jj++)
            pb[i * 4 + jj] = Bcol[(size_t)(kk2 * 16 + i * 4 + jj) * N];
    {
        uint32_t h0,l0,h1,l1,h2,l2,h3,l3;
        split2(pa0.x, pa0.y, h0, l0); split2(pa0.z, pa0.w, h1, l1);
        split2(pa1.x, pa1.y, h2, l2); split2(pa1.z, pa1.w, h3, l3);
        *(uint4*)&sh[OFF_AH(0) + arow * KST + akof] = make_uint4(h0,h1,h2,h3);
        *(uint4*)&sh[OFF_AL(0) + arow * KST + akof] = make_uint4(l0,l1,l2,l3);
        #pragma unroll
        for (int i = 0; i < 4; i++) {
            const int kb = kk2 * 16 + i * 4;
            uint32_t bh0,bl0,bh1,bl1;
            split2(pb[i*4+0], pb[i*4+1], bh0, bl0);
            split2(pb[i*4+2], pb[i*4+3], bh1, bl1);
            *(uint2*)&sh[OFF_BH(0) + nB * KST + kb] = make_uint2(bh0, bh1);
            *(uint2*)&sh[OFF_BL(0) + nB * KST + kb] = make_uint2(bl0, bl1);
        }
    }
    __syncthreads();

    float acc[2][4][4] = {};

    const int nkt = K >> 5;
    for (int j = 0; j < nkt; j++) {
        const int cur = j & 1;
        const bool more = (j + 1 < nkt);
        if (more) {
            const int k0 = (j + 1) << 5;
            pa0 = *(const float4*)(Agp + k0);
            pa1 = *(const float4*)(Agp + k0 + 4);
            #pragma unroll
            for (int i = 0; i < 4; i++)
                #pragma unroll
                for (int jj = 0; jj < 4; jj++)
                    pb[i * 4 + jj] = Bcol[(size_t)(k0 + kk2 * 16 + i * 4 + jj) * N];
        }
        {
            const uint32_t aHiB = sbase + (uint32_t)OFF_AH(cur) * 2u;
            const uint32_t aLoB = sbase + (uint32_t)OFF_AL(cur) * 2u;
            const uint32_t bHiB = sbase + (uint32_t)OFF_BH(cur) * 2u;
            const uint32_t bLoB = sbase + (uint32_t)OFF_BL(cur) * 2u;
            #pragma unroll
            for (int ks = 0; ks < 2; ks++) {
                const uint32_t kadd = (uint32_t)ks * 32u;
                uint32_t bh[2][4], bl[2][4], ah[2][4], al[2][4];
                ldsm4(bh[0][0], bh[0][1], bh[0][2], bh[0][3], bHiB + boff0 + kadd);
                ldsm4(bh[1][0], bh[1][1], bh[1][2], bh[1][3], bHiB + boff1 + kadd);
                ldsm4(bl[0][0], bl[0][1], bl[0][2], bl[0][3], bLoB + boff0 + kadd);
                ldsm4(bl[1][0], bl[1][1], bl[1][2], bl[1][3], bLoB + boff1 + kadd);
                ldsm4(ah[0][0], ah[0][1], ah[0][2], ah[0][3], aHiB + aoff0 + kadd);
                ldsm4(ah[1][0], ah[1][1], ah[1][2], ah[1][3], aHiB + aoff1 + kadd);
                ldsm4(al[0][0], al[0][1], al[0][2], al[0][3], aLoB + aoff0 + kadd);
                ldsm4(al[1][0], al[1][1], al[1][2], al[1][3], aLoB + aoff1 + kadd);
                #pragma unroll
                for (int mi = 0; mi < 2; mi++)
                    #pragma unroll
                    for (int ni = 0; ni < 4; ni++)
                        mma_f16(acc[mi][ni], ah[mi], &bh[ni >> 1][(ni & 1) * 2]);
                #pragma unroll
                for (int mi = 0; mi < 2; mi++)
                    #pragma unroll
                    for (int ni = 0; ni < 4; ni++)
                        mma_f16(acc[mi][ni], ah[mi], &bl[ni >> 1][(ni & 1) * 2]);
                #pragma unroll
                for (int mi = 0; mi < 2; mi++)
                    #pragma unroll
                    for (int ni = 0; ni < 4; ni++)
                        mma_f16(acc[mi][ni], al[mi], &bh[ni >> 1][(ni & 1) * 2]);
            }
        }
        if (more) {
            const int nxt = cur ^ 1;
            uint32_t h0,l0,h1,l1,h2,l2,h3,l3;
            split2(pa0.x, pa0.y, h0, l0); split2(pa0.z, pa0.w, h1, l1);
            split2(pa1.x, pa1.y, h2, l2); split2(pa1.z, pa1.w, h3, l3);
            *(uint4*)&sh[OFF_AH(nxt) + arow * KST + akof] = make_uint4(h0,h1,h2,h3);
            *(uint4*)&sh[OFF_AL(nxt) + arow * KST + akof] = make_uint4(l0,l1,l2,l3);
            #pragma unroll
            for (int i = 0; i < 4; i++) {
                const int kb = kk2 * 16 + i * 4;
                uint32_t bh0,bl0,bh1,bl1;
                split2(pb[i*4+0], pb[i*4+1], bh0, bl0);
                split2(pb[i*4+2], pb[i*4+3], bh1, bl1);
                *(uint2*)&sh[OFF_BH(nxt) + nB * KST + kb] = make_uint2(bh0, bh1);
                *(uint2*)&sh[OFF_BL(nxt) + nB * KST + kb] = make_uint2(bl0, bl1);
            }
            __syncthreads();
        }
    }

    #pragma unroll
    for (int mi = 0; mi < 2; mi++) {
        #pragma unroll
        for (int half = 0; half < 2; half++) {
            const int row = m0 + wm * 32 + mi * 16 + gid + half * 8;
            #pragma unroll
            for (int ni = 0; ni < 4; ni++) {
                const int col = n0 + wn * 32 + ni * 8 + tig * 2;
                float vx = acc[mi][ni][half * 2 + 0] + bias[col];
                float vy = acc[mi][ni][half * 2 + 1] + bias[col + 1];
                float* dst = C + (size_t)row * N + col;
                if (EPI == 1) {
                    vx = gelu1(vx); vy = gelu1(vy);
                } else if (EPI == 2) {
                    const float2 rr = *(const float2*)(res + (size_t)row * N + col);
                    vx += rr.x; vy += rr.y;
                }
                *(float2*)dst = make_float2(vx, vy);
            }
        }
    }
}

// ---------------------------------------------------------------------------
// Flash attention: block per (b,head), thread per query row; writes HALVES.
// ---------------------------------------------------------------------------
#define KVP 68
#define SMEM_ATTN (2 * 128 * KVP * 4)

__global__ void __launch_bounds__(128) attn_flash(const float* __restrict__ qkv,
                                                  __half* __restrict__ oh,
                                                  __half* __restrict__ ol)
{
    const int bh = blockIdx.x;
    const int b = bh >> 3, hh = bh & 7;
    const int t = threadIdx.x;
    const float* base = qkv + (size_t)b * 128 * 1536 + hh * 64;

    extern __shared__ float kv[];
    float (*Ks)[KVP] = (float(*)[KVP])kv;
    float (*Vs)[KVP] = (float(*)[KVP])(kv + 128 * KVP);

    {
        const float* kr = base + (size_t)t * 1536 + 512;
        const float* vr = kr + 512;
        #pragma unroll
        for (int d4 = 0; d4 < 16; d4++) {
            *(float4*)&Ks[t][d4 * 4] = *(const float4*)(kr + d4 * 4);
            *(float4*)&Vs[t][d4 * 4] = *(const float4*)(vr + d4 * 4);
        }
    }
    float q[64];
    {
        const float* qr = base + (size_t)t * 1536;
        #pragma unroll
        for (int d4 = 0; d4 < 16; d4++) {
            float4 f = *(const float4*)(qr + d4 * 4);
            q[d4 * 4 + 0] = f.x; q[d4 * 4 + 1] = f.y;
            q[d4 * 4 + 2] = f.z; q[d4 * 4 + 3] = f.w;
        }
    }
    __syncthreads();

    float oacc[64];
    #pragma unroll
    for (int d = 0; d < 64; d++) oacc[d] = 0.f;
    float m = -1e30f, l = 0.f;

    for (int j = 0; j <= t; j++) {
        float s = 0.f;
        #pragma unroll
        for (int d4 = 0; d4 < 16; d4++) {
            float4 k4 = *(const float4*)&Ks[j][d4 * 4];
            s += q[d4 * 4 + 0] * k4.x + q[d4 * 4 + 1] * k4.y
               + q[d4 * 4 + 2] * k4.z + q[d4 * 4 + 3] * k4.w;
        }
        s *= 0.125f;
        const float nm = fmaxf(m, s);
        const float sc = __expf(m - nm), e = __expf(s - nm);
        l = l * sc + e;
        m = nm;
        #pragma unroll
        for (int d4 = 0; d4 < 16; d4++) {
            float4 v4 = *(const float4*)&Vs[j][d4 * 4];
            oacc[d4 * 4 + 0] = oacc[d4 * 4 + 0] * sc + e * v4.x;
            oacc[d4 * 4 + 1] = oacc[d4 * 4 + 1] * sc + e * v4.y;
            oacc[d4 * 4 + 2] = oacc[d4 * 4 + 2] * sc + e * v4.z;
            oacc[d4 * 4 + 3] = oacc[d4 * 4 + 3] * sc + e * v4.w;
        }
    }
    const float inv = 1.0f / l;
    const size_t oo = ((size_t)b * 128 + t) * 512 + hh * 64;
    #pragma unroll
    for (int d4 = 0; d4 < 16; d4++) {
        uint32_t h0, l0, h1, l1;
        split2(oacc[d4 * 4 + 0] * inv, oacc[d4 * 4 + 1] * inv, h0, l0);
        split2(oacc[d4 * 4 + 2] * inv, oacc[d4 * 4 + 3] * inv, h1, l1);
        *(uint2*)&oh[oo + d4 * 4] = make_uint2(h0, h1);
        *(uint2*)&ol[oo + d4 * 4] = make_uint2(l0, l1);
    }
}

// ---------------------------------------------------------------------------
__global__ void patchnorm_kernel(const float* __restrict__ x, float* __restrict__ y)
{
    const int warp = threadIdx.x >> 5, lane = threadIdx.x & 31;
    const int row = blockIdx.x * 8 + warp;
    const float* xr = x + (size_t)row * 128;
    float4 f = *(const float4*)(xr + lane * 4);
    float s = f.x + f.y + f.z + f.w;
    #pragma unroll
    for (int o = 16; o; o >>= 1) s += __shfl_xor_sync(0xffffffffu, s, o);
    const float mu = s * (1.0f / 128.0f);
    float q = (f.x - mu) * (f.x - mu) + (f.y - mu) * (f.y - mu)
            + (f.z - mu) * (f.z - mu) + (f.w - mu) * (f.w - mu);
    #pragma unroll
    for (int o = 16; o; o >>= 1) q += __shfl_xor_sync(0xffffffffu, q, o);
    const float rs = rsqrtf(q * (1.0f / 128.0f) + 1e-6f);
    float4 r = make_float4((f.x - mu) * rs, (f.y - mu) * rs, (f.z - mu) * rs, (f.w - mu) * rs);
    *(float4*)(y + (size_t)row * 128 + lane * 4) = r;
}

// LN -> half hi/lo only. GATE: also compute softmax gate + top-2 routing.
template<bool GATE>
__global__ void ln512g_kernel(const float* __restrict__ x,
                              __half* __restrict__ yh, __half* __restrict__ yl,
                              const float* __restrict__ g, const float* __restrict__ b,
                              const float* __restrict__ gw, const float* __restrict__ gb,
                              int* __restrict__ cnt, int* __restrict__ idx,
                              float* __restrict__ rw)
{
    const int warp = threadIdx.x >> 5, lane = threadIdx.x & 31;
    const int row = blockIdx.x * 8 + warp;
    const float* xr = x + (size_t)row * 512;
    float v[16];
    float s = 0.f;
    #pragma unroll
    for (int c = 0; c < 4; c++) {
        float4 f = *(const float4*)(xr + c * 128 + lane * 4);
        v[c * 4 + 0] = f.x; v[c * 4 + 1] = f.y; v[c * 4 + 2] = f.z; v[c * 4 + 3] = f.w;
        s += f.x + f.y + f.z + f.w;
    }
    #pragma unroll
    for (int o = 16; o; o >>= 1) s += __shfl_xor_sync(0xffffffffu, s, o);
    const float mu = s * (1.0f / 512.0f);
    float q = 0.f;
    #pragma unroll
    for (int k = 0; k < 16; k++) { float d = v[k] - mu; q += d * d; }
    #pragma unroll
    for (int o = 16; o; o >>= 1) q += __shfl_xor_sync(0xffffffffu, q, o);
    const float rs = rsqrtf(q * (1.0f / 512.0f) + 1e-5f);
    #pragma unroll
    for (int c = 0; c < 4; c++) {
        const int col = c * 128 + lane * 4;
        float4 gg = *(const float4*)(g + col);
        float4 bb = *(const float4*)(b + col);
        float4 r;
        r.x = gg.x * (v[c * 4 + 0] - mu) * rs + bb.x;
        r.y = gg.y * (v[c * 4 + 1] - mu) * rs + bb.y;
        r.z = gg.z * (v[c * 4 + 2] - mu) * rs + bb.z;
        r.w = gg.w * (v[c * 4 + 3] - mu) * rs + bb.w;
        v[c * 4 + 0] = r.x; v[c * 4 + 1] = r.y;
        v[c * 4 + 2] = r.z; v[c * 4 + 3] = r.w;
        uint32_t h0, l0, h1, l1;
        split2(r.x, r.y, h0, l0);
        split2(r.z, r.w, h1, l1);
        *(uint2*)&yh[(size_t)row * 512 + col] = make_uint2(h0, h1);
        *(uint2*)&yl[(size_t)row * 512 + col] = make_uint2(l0, l1);
    }
    if (GATE) {
        float a0 = 0.f, a1 = 0.f, a2 = 0.f, a3 = 0.f;
        #pragma unroll
        for (int c = 0; c < 4; c++)
            #pragma unroll
            for (int j = 0; j < 4; j++) {
                const int col = c * 128 + lane * 4 + j;
                const float hv = v[c * 4 + j];
                float4 w = *(const float4*)(gw + (size_t)col * 4);
                a0 += hv * w.x; a1 += hv * w.y; a2 += hv * w.z; a3 += hv * w.w;
            }
        #pragma unroll
        for (int o = 16; o; o >>= 1) {
            a0 += __shfl_xor_sync(0xffffffffu, a0, o);
            a1 += __shfl_xor_sync(0xffffffffu, a1, o);
            a2 += __shfl_xor_sync(0xffffffffu, a2, o);
            a3 += __shfl_xor_sync(0xffffffffu, a3, o);
        }
        if (lane == 0) {
            float p[4] = {a0 + gb[0], a1 + gb[1], a2 + gb[2], a3 + gb[3]};
            const float mx = fmaxf(fmaxf(p[0], p[1]), fmaxf(p[2], p[3]));
            float ss = 0.f;
            #pragma unroll
            for (int e = 0; e < 4; e++) { p[e] = expf(p[e] - mx); ss += p[e]; }
            const float invs = 1.0f / ss;
            #pragma unroll
            for (int e = 0; e < 4; e++) p[e] *= invs;
            int i0 = 0;
            #pragma unroll
            for (int e = 1; e < 4; e++) if (p[e] > p[i0]) i0 = e;
            int i1 = -1;
            #pragma unroll
            for (int e = 0; e < 4; e++) if (e != i0 && (i1 < 0 || p[e] > p[i1])) i1 = e;
            int s0 = atomicAdd(&cnt[i0], 1);
            idx[i0 * T_TOK + s0] = row; rw[i0 * T_TOK + s0] = p[i0];
            int s1 = atomicAdd(&cnt[i1], 1);
            idx[i1 * T_TOK + s1] = row; rw[i1 * T_TOK + s1] = p[i1];
        }
    }
}

__global__ void freqadd_kernel(float* __restrict__ h, const float* __restrict__ emb,
                               const int* __restrict__ fid)
{
    const int i = blockIdx.x * 256 + threadIdx.x;
    const int row = i >> 9, d = i & 511, b = row >> 7;
    h[i] += emb[(size_t)fid[b] * 512 + d];
}

__global__ void zero_cnt_kernel(int* cnt)
{
    if (threadIdx.x < 4) cnt[threadIdx.x] = 0;
}

__global__ void head_kernel(const float* __restrict__ h,
                            const float* __restrict__ fng, const float* __restrict__ fnb,
                            const float* __restrict__ hg,  const float* __restrict__ hb,
                            const float* __restrict__ hw,  const float* __restrict__ hbias,
                            float* __restrict__ out, int out_size)
{
    const int warp = threadIdx.x >> 5, lane = threadIdx.x & 31;
    const int b = warp;
    const float* xr = h + ((size_t)b * 128 + 127) * 512;
    float v[16];
    float s = 0.f;
    #pragma unroll
    for (int c = 0; c < 4; c++) {
        float4 f = *(const float4*)(xr + c * 128 + lane * 4);
        v[c * 4 + 0] = f.x; v[c * 4 + 1] = f.y; v[c * 4 + 2] = f.z; v[c * 4 + 3] = f.w;
        s += f.x + f.y + f.z + f.w;
    }
    #pragma unroll
    for (int o = 16; o; o >>= 1) s += __shfl_xor_sync(0xffffffffu, s, o);
    float mu = s * (1.0f / 512.0f);
    float q = 0.f;
    #pragma unroll
    for (int k = 0; k < 16; k++) { float d = v[k] - mu; q += d * d; }
    #pragma unroll
    for (int o = 16; o; o >>= 1) q += __shfl_xor_sync(0xffffffffu, q, o);
    float rs = rsqrtf(q * (1.0f / 512.0f) + 1e-5f);
    #pragma unroll
    for (int c = 0; c < 4; c++)
        #pragma unroll
        for (int j = 0; j < 4; j++) {
            const int col = c * 128 + lane * 4 + j;
            v[c * 4 + j] = fng[col] * (v[c * 4 + j] - mu) * rs + fnb[col];
        }
    s = 0.f;
    #pragma unroll
    for (int k = 0; k < 16; k++) s += v[k];
    #pragma unroll
    for (int o = 16; o; o >>= 1) s += __shfl_xor_sync(0xffffffffu, s, o);
    mu = s * (1.0f / 512.0f);
    q = 0.f;
    #pragma unroll
    for (int k = 0; k < 16; k++) { float d = v[k] - mu; q += d * d; }
    #pragma unroll
    for (int o = 16; o; o >>= 1) q += __shfl_xor_sync(0xffffffffu, q, o);
    rs = rsqrtf(q * (1.0f / 512.0f) + 1e-5f);
    float dot = 0.f;
    #pragma unroll
    for (int c = 0; c < 4; c++)
        #pragma unroll
        for (int j = 0; j < 4; j++) {
            const int col = c * 128 + lane * 4 + j;
            const float hl = hg[col] * (v[c * 4 + j] - mu) * rs + hb[col];
            dot += hl * hw[col];
        }
    #pragma unroll
    for (int o = 16; o; o >>= 1) dot += __shfl_xor_sync(0xffffffffu, dot, o);
    if (lane == 0) {
        const float logit = dot + hbias[0];
        if (out_size >= 32) {
            out[b] = logit;
            out[16 + b] = 1.0f / (1.0f + expf(-logit));
        } else {
            out[b] = logit;
        }
    }
}

// ---------------------------------------------------------------------------
extern "C" void kernel_launch(void* const* d_in, const int* in_sizes, int n_in,
                              void* d_out, int out_size)
{
    const float* x        = (const float*)d_in[0];
    const int*   fid      = (const int*)  d_in[1];
    const float* ir_w1    = (const float*)d_in[2];
    const float* ir_b1    = (const float*)d_in[3];
    const float* ir_w2    = (const float*)d_in[4];
    const float* ir_b2    = (const float*)d_in[5];
    const float* p2m_w    = (const float*)d_in[6];
    const float* p2m_b    = (const float*)d_in[7];
    const float* freq_emb = (const float*)d_in[8];
    const float* ln1_g    = (const float*)d_in[9];
    const float* ln1_b    = (const float*)d_in[10];
    const float* qkv_w    = (const float*)d_in[11];
    const float* qkv_b    = (const float*)d_in[12];
    const float* out_w    = (const float*)d_in[13];
    const float* out_b    = (const float*)d_in[14];
    const float* ln2_g    = (const float*)d_in[15];
    const float* ln2_b    = (const float*)d_in[16];
    const float* gate_w   = (const float*)d_in[17];
    const float* gate_b   = (const float*)d_in[18];
    const float* exp_w1   = (const float*)d_in[19];
    const float* exp_b1   = (const float*)d_in[20];
    const float* exp_w2   = (const float*)d_in[21];
    const float* exp_b2   = (const float*)d_in[22];
    const float* fn_g     = (const float*)d_in[23];
    const float* fn_b     = (const float*)d_in[24];
    const float* head_g   = (const float*)d_in[25];
    const float* head_b   = (const float*)d_in[26];
    const float* head_w   = (const float*)d_in[27];
    const float* head_bias= (const float*)d_in[28];

    float *patches, *tmp, *hp, *h, *qkv, *rw;
    int *cnt, *idx;
    __half *qkvTh, *qkvTl, *outTh, *outTl, *e1Th, *e1Tl, *e2Th, *e2Tl;
    __half *hnh, *hnl, *ath, *atl, *ehh, *ehl;
    cudaGetSymbolAddress((void**)&patches, g_patches);
    cudaGetSymbolAddress((void**)&tmp,     g_tmp);
    cudaGetSymbolAddress((void**)&hp,      g_hp);
    cudaGetSymbolAddress((void**)&h,       g_h);
    cudaGetSymbolAddress((void**)&qkv,     g_qkv);
    cudaGetSymbolAddress((void**)&cnt,     g_cnt);
    cudaGetSymbolAddress((void**)&idx,     g_idx);
    cudaGetSymbolAddress((void**)&rw,      g_rw);
    cudaGetSymbolAddress((void**)&qkvTh,   g_qkvTh);
    cudaGetSymbolAddress((void**)&qkvTl,   g_qkvTl);
    cudaGetSymbolAddress((void**)&outTh,   g_outTh);
    cudaGetSymbolAddress((void**)&outTl,   g_outTl);
    cudaGetSymbolAddress((void**)&e1Th,    g_e1Th);
    cudaGetSymbolAddress((void**)&e1Tl,    g_e1Tl);
    cudaGetSymbolAddress((void**)&e2Th,    g_e2Th);
    cudaGetSymbolAddress((void**)&e2Tl,    g_e2Tl);
    cudaGetSymbolAddress((void**)&hnh,     g_hnh);
    cudaGetSymbolAddress((void**)&hnl,     g_hnl);
    cudaGetSymbolAddress((void**)&ath,     g_ath);
    cudaGetSymbolAddress((void**)&atl,     g_atl);
    cudaGetSymbolAddress((void**)&ehh,     g_ehh);
    cudaGetSymbolAddress((void**)&ehl,     g_ehl);

    cudaFuncSetAttribute(mma_gemm<0>, cudaFuncAttributeMaxDynamicSharedMemorySize, SMEM_MMA);
    cudaFuncSetAttribute(mma_gemm<1>, cudaFuncAttributeMaxDynamicSharedMemorySize, SMEM_MMA);
    cudaFuncSetAttribute(mma_gemm<2>, cudaFuncAttributeMaxDynamicSharedMemorySize, SMEM_MMA);
    cudaFuncSetAttribute(hgemm<0,false,false,false,1>, cudaFuncAttributeMaxDynamicSharedMemorySize, SMEM_HG);
    cudaFuncSetAttribute(hgemm<7,false,false,false,2>, cudaFuncAttributeMaxDynamicSharedMemorySize, SMEM_HG);
    cudaFuncSetAttribute(hgemm<6,true,true,true,1>,    cudaFuncAttributeMaxDynamicSharedMemorySize, SMEM_HG);
    cudaFuncSetAttribute(hgemm<5,false,true,true,1>,   cudaFuncAttributeMaxDynamicSharedMemorySize, SMEM_HG);
    cudaFuncSetAttribute(attn_flash, cudaFuncAttributeMaxDynamicSharedMemorySize, SMEM_ATTN);

    // ---- pre-split all weights ----
    wsplitT<<<dim3(24, 16, 12), 256>>>(qkv_w,  qkvTh, qkvTl, 512, 1536);
    wsplitT<<<dim3(8,  16, 12), 256>>>(out_w,  outTh, outTl, 512, 512);
    wsplitT<<<dim3(32, 16, 48), 256>>>(exp_w1, e1Th,  e1Tl,  512, 2048);
    wsplitT<<<dim3(8,  64, 48), 256>>>(exp_w2, e2Th,  e2Tl,  2048, 512);

    // ---- front end (fp32 path) ----
    patchnorm_kernel<<<256, 256>>>(x, patches);
    mma_gemm<1><<<dim3(4, 32), 256, SMEM_MMA>>>(patches, ir_w1, ir_b1, tmp,
        T_TOK, 512, 128, nullptr);
    mma_gemm<2><<<dim3(1, 32), 256, SMEM_MMA>>>(tmp, ir_w2, ir_b2, hp,
        T_TOK, 128, 512, patches);
    mma_gemm<0><<<dim3(4, 32), 256, SMEM_MMA>>>(hp, p2m_w, p2m_b, h,
        T_TOK, 512, 128, nullptr);
    freqadd_kernel<<<(T_TOK * 512) / 256, 256>>>(h, freq_emb, fid);

    const size_t EHZ = (size_t)T_TOK * HDIM;

    for (int l = 0; l < 12; l++) {
        // attention
        ln512g_kernel<false><<<256, 256>>>(h, hnh, hnl,
            ln1_g + (size_t)l * 512, ln1_b + (size_t)l * 512,
            nullptr, nullptr, nullptr, nullptr, nullptr);
        hgemm<0,false,false,false,1><<<dim3(12, 32), 256, SMEM_HG>>>(
            hnh, hnl, qkvTh + (size_t)l * 1536 * 512, qkvTl + (size_t)l * 1536 * 512,
            qkv_b + (size_t)l * 1536, qkv, nullptr, nullptr,
            T_TOK, 1536, 512, nullptr, nullptr, nullptr, 0, 0);
        attn_flash<<<128, 128, SMEM_ATTN>>>(qkv, ath, atl);
        hgemm<7,false,false,false,2><<<dim3(4, 32, 2), 256, SMEM_HG>>>(
            ath, atl, outTh + (size_t)l * 512 * 512, outTl + (size_t)l * 512 * 512,
            out_b + (size_t)l * 512, h, nullptr, nullptr,
            T_TOK, 512, 512, nullptr, nullptr, nullptr, 0, 0);
        // sparse MoE: LN + gate + routing fused
        zero_cnt_kernel<<<1, 32>>>(cnt);
        ln512g_kernel<true><<<256, 256>>>(h, hnh, hnl,
            ln2_g + (size_t)l * 512, ln2_b + (size_t)l * 512,
            gate_w + (size_t)l * 512 * 4, gate_b + (size_t)l * 4, cnt, idx, rw);
        hgemm<6,true,true,true,1><<<dim3(16, 32, 4), 256, SMEM_HG>>>(
            hnh, hnl, e1Th + (size_t)l * 4 * 2048 * 512, e1Tl + (size_t)l * 4 * 2048 * 512,
            exp_b1 + (size_t)l * 4 * 2048, nullptr, ehh, ehl,
            T_TOK, 2048, 512, idx, nullptr, cnt, 0, EHZ);
        hgemm<5,false,true,true,1><<<dim3(4, 32, 4), 256, SMEM_HG>>>(
            ehh, ehl, e2Th + (size_t)l * 4 * 512 * 2048, e2Tl + (size_t)l * 4 * 512 * 2048,
            exp_b2 + (size_t)l * 4 * 512, h, nullptr, nullptr,
            T_TOK, 512, 2048, idx, rw, cnt, EHZ, 0);
    }

    head_kernel<<<1, 512>>>(h, fn_g, fn_b, head_g, head_b, head_w, head_bias,
                            (float*)d_out, out_size);
}

// round 16
// speedup vs baseline: 1.0707x; 1.0007x over previous
#include <cuda_runtime.h>
#include <cuda_fp16.h>
#include <math.h>
#include <stdint.h>

// ---------------------------------------------------------------------------
// B=16, S=2048, C=8, P=16 -> N=128 patches, T=2048 tokens
// PD=128, IRH=512, D=512, NH=8, dh=64, L=12, E=4, H=2048, top-2 routing
// Split-precision fp16 HMMA GEMMs, pre-split hi/lo operands, fused LN+gate,
// split-K=4 out-projection, counter zeroing fused into attention LN.
// ---------------------------------------------------------------------------
#define T_TOK 2048
#define DIM   512
#define HDIM  2048

__device__ float g_patches[T_TOK * 128];
__device__ float g_tmp    [T_TOK * 512];
__device__ float g_hp     [T_TOK * 128];
__device__ float g_h      [T_TOK * DIM];
__device__ float g_qkv    [T_TOK * 3 * DIM];
__device__ int   g_cnt    [4];
__device__ int   g_idx    [4 * T_TOK];
__device__ float g_rw     [4 * T_TOK];

__device__ __half g_qkvTh[12 * 1536 * 512];
__device__ __half g_qkvTl[12 * 1536 * 512];
__device__ __half g_outTh[12 * 512 * 512];
__device__ __half g_outTl[12 * 512 * 512];
__device__ __half g_e1Th [48 * 2048 * 512];
__device__ __half g_e1Tl [48 * 2048 * 512];
__device__ __half g_e2Th [48 * 512 * 2048];
__device__ __half g_e2Tl [48 * 512 * 2048];
__device__ __half g_hnh  [T_TOK * 512];
__device__ __half g_hnl  [T_TOK * 512];
__device__ __half g_ath  [T_TOK * 512];
__device__ __half g_atl  [T_TOK * 512];
__device__ __half g_ehh  [4 * T_TOK * 2048];
__device__ __half g_ehl  [4 * T_TOK * 2048];

// ---- helpers ---------------------------------------------------------------
__device__ __forceinline__ void split2(float f0, float f1, uint32_t& hi, uint32_t& lo) {
    __half2 h = __floats2half2_rn(f0, f1);
    float2 hf = __half22float2(h);
    __half2 l = __floats2half2_rn(f0 - hf.x, f1 - hf.y);
    hi = *(uint32_t*)&h;
    lo = *(uint32_t*)&l;
}
__device__ __forceinline__ void mma_f16(float* d, const uint32_t* a, const uint32_t* b) {
    asm volatile(
        "mma.sync.aligned.m16n8k16.row.col.f32.f16.f16.f32 "
        "{%0,%1,%2,%3}, {%4,%5,%6,%7}, {%8,%9}, {%0,%1,%2,%3};"
        : "+f"(d[0]), "+f"(d[1]), "+f"(d[2]), "+f"(d[3])
        : "r"(a[0]), "r"(a[1]), "r"(a[2]), "r"(a[3]), "r"(b[0]), "r"(b[1]));
}
__device__ __forceinline__ void ldsm4(uint32_t& r0, uint32_t& r1, uint32_t& r2,
                                      uint32_t& r3, uint32_t addr) {
    asm volatile("ldmatrix.sync.aligned.m8n8.x4.shared.b16 {%0,%1,%2,%3}, [%4];"
                 : "=r"(r0), "=r"(r1), "=r"(r2), "=r"(r3) : "r"(addr));
}
__device__ __forceinline__ void cpasync16(uint32_t s, const void* g) {
    asm volatile("cp.async.ca.shared.global [%0], [%1], 16;" :: "r"(s), "l"(g));
}
#define CP_COMMIT() asm volatile("cp.async.commit_group;" ::: "memory")
#define CP_WAIT(n)  asm volatile("cp.async.wait_group %0;" :: "n"(n) : "memory")

__device__ __forceinline__ float gelu1(float v) {
    return 0.5f * v * (1.0f + erff(v * 0.70710678118654752f));
}

// ---------------------------------------------------------------------------
// Weight split + transpose: w [K][N] fp32 -> whi/wlo [N][K] halves.
// ---------------------------------------------------------------------------
__global__ void __launch_bounds__(256) wsplitT(const float* __restrict__ w,
        __half* __restrict__ whi, __half* __restrict__ wlo, int K, int N)
{
    const size_t zoff = (size_t)blockIdx.z * K * N;
    w += zoff; whi += zoff; wlo += zoff;
    const int n0 = blockIdx.x * 64, k0 = blockIdx.y * 32;
    __shared__ float tile[32][65];
    const int t = threadIdx.x;
    #pragma unroll
    for (int i = 0; i < 8; i++) {
        const int e = t + i * 256;
        const int k = e >> 6, n = e & 63;
        tile[k][n] = w[(size_t)(k0 + k) * N + n0 + n];
    }
    __syncthreads();
    const int n = t >> 2, c = (t & 3) * 8;
    uint32_t hi[4], lo[4];
    #pragma unroll
    for (int i = 0; i < 4; i++)
        split2(tile[c + 2 * i][n], tile[c + 2 * i + 1][n], hi[i], lo[i]);
    const size_t o = (size_t)(n0 + n) * K + k0 + c;
    *(uint4*)&whi[o] = make_uint4(hi[0], hi[1], hi[2], hi[3]);
    *(uint4*)&wlo[o] = make_uint4(lo[0], lo[1], lo[2], lo[3]);
}

// ---------------------------------------------------------------------------
// hgemm: pre-split halves, 64x128 tile, BK=32, 2-stage cp.async.
// EPI: 0 store fp32, 5 atomic scatter, 6 gelu->half hi/lo, 7 atomicAdd (+bias z0)
// SK: split-K count (blockIdx.z = k slice when SK>1; EXPZ must be false)
// ---------------------------------------------------------------------------
#define KST 40
#define HG_STG 15360
#define SMEM_HG (2 * HG_STG * 2)

template<int EPI, bool GA, bool GUARD, bool EXPZ, int SK>
__global__ void __launch_bounds__(256, 2) hgemm(
    const __half* __restrict__ Ah, const __half* __restrict__ Al,
    const __half* __restrict__ Bh, const __half* __restrict__ Bl,
    const float* __restrict__ bias,
    float* __restrict__ C, __half* __restrict__ Ch, __half* __restrict__ Cl,
    int M, int N, int K,
    const int* __restrict__ idx, const float* __restrict__ rw,
    const int* __restrict__ cnt, size_t zA, size_t zC)
{
    if (EXPZ) {
        const int z = blockIdx.z;
        Ah += (size_t)z * zA; Al += (size_t)z * zA;
        Bh += (size_t)z * (size_t)K * N; Bl += (size_t)z * (size_t)K * N;
        bias += (size_t)z * N;
        if (EPI == 6) { Ch += (size_t)z * zC; Cl += (size_t)z * zC; }
        else          { C  += (size_t)z * zC; }
        idx += z * T_TOK;
        if (rw) rw += z * T_TOK;
        cnt += z;
    }
    int koff = 0;
    float bsc = 1.f;
    if (SK > 1) {
        koff = blockIdx.z * (K / SK);
        if (blockIdx.z != 0) bsc = 0.f;
    }
    const int klen = (SK > 1) ? (K / SK) : K;

    const int t = threadIdx.x, wid = t >> 5, lane = t & 31;
    const int m0 = blockIdx.y * 64, n0 = blockIdx.x * 128;

    int cq = M;
    if (GUARD) { cq = *cnt; if (m0 >= cq) return; }

    extern __shared__ __half sh[];
    const uint32_t sbase = (uint32_t)__cvta_generic_to_shared(sh);

    const int arow = t >> 2, acof = (t & 3) * 8;
    int garow = m0 + arow;
    if (GA) garow = (garow < cq) ? idx[garow] : idx[0];
    const __half* Asrc_h = Ah + (size_t)garow * K + koff + acof;
    const __half* Asrc_l = Al + (size_t)garow * K + koff + acof;
    const int brow = t >> 1;
    const int bcof0 = ((2 * t) & 3) * 8, bcof1 = ((2 * t + 1) & 3) * 8;
    const __half* Bsrc_h = Bh + (size_t)(n0 + brow) * K + koff;
    const __half* Bsrc_l = Bl + (size_t)(n0 + brow) * K + koff;

    const uint32_t adst  = (uint32_t)(arow * KST + acof) * 2u;
    const uint32_t bdst0 = (uint32_t)(brow * KST + bcof0) * 2u;
    const uint32_t bdst1 = (uint32_t)(brow * KST + bcof1) * 2u;

    auto issue = [&](int s, int k0) {
        const uint32_t sb = sbase + (uint32_t)(s * HG_STG) * 2u;
        cpasync16(sb + adst,               Asrc_h + k0);
        cpasync16(sb + 2560u * 2u + adst,  Asrc_l + k0);
        cpasync16(sb + 5120u * 2u + bdst0, Bsrc_h + k0 + bcof0);
        cpasync16(sb + 5120u * 2u + bdst1, Bsrc_h + k0 + bcof1);
        cpasync16(sb + 10240u * 2u + bdst0, Bsrc_l + k0 + bcof0);
        cpasync16(sb + 10240u * 2u + bdst1, Bsrc_l + k0 + bcof1);
        CP_COMMIT();
    };

    const int wm = wid >> 2, wn = wid & 3;
    const int gid = lane >> 2, tig = lane & 3;
    const int l7 = lane & 7, q8 = lane >> 3;
    const int A_row = (q8 & 1) * 8 + l7, A_k = (q8 >> 1) * 8;
    const int B_row = (q8 >> 1) * 8 + l7, B_k = (q8 & 1) * 8;
    const uint32_t aoff0 = (uint32_t)((wm * 32 + A_row) * KST + A_k) * 2u;
    const uint32_t aoff1 = aoff0 + 16u * KST * 2u;
    const uint32_t boff0 = (uint32_t)((wn * 32 + B_row) * KST + B_k) * 2u;
    const uint32_t boff1 = boff0 + 16u * KST * 2u;

    float acc[2][4][4] = {};

    const int nkt = klen >> 5;
    issue(0, 0);
    for (int j = 0; j < nkt; j++) {
        if (j + 1 < nkt) { issue((j + 1) & 1, (j + 1) << 5); CP_WAIT(1); }
        else             { CP_WAIT(0); }
        __syncthreads();
        const uint32_t sb = sbase + (uint32_t)((j & 1) * HG_STG) * 2u;
        const uint32_t aHiB = sb, aLoB = sb + 2560u * 2u;
        const uint32_t bHiB = sb + 5120u * 2u, bLoB = sb + 10240u * 2u;
        #pragma unroll
        for (int ks = 0; ks < 2; ks++) {
            const uint32_t kadd = (uint32_t)ks * 32u;
            uint32_t bh[2][4], bl[2][4], ah[2][4], al[2][4];
            ldsm4(bh[0][0], bh[0][1], bh[0][2], bh[0][3], bHiB + boff0 + kadd);
            ldsm4(bh[1][0], bh[1][1], bh[1][2], bh[1][3], bHiB + boff1 + kadd);
            ldsm4(bl[0][0], bl[0][1], bl[0][2], bl[0][3], bLoB + boff0 + kadd);
            ldsm4(bl[1][0], bl[1][1], bl[1][2], bl[1][3], bLoB + boff1 + kadd);
            ldsm4(ah[0][0], ah[0][1], ah[0][2], ah[0][3], aHiB + aoff0 + kadd);
            ldsm4(ah[1][0], ah[1][1], ah[1][2], ah[1][3], aHiB + aoff1 + kadd);
            ldsm4(al[0][0], al[0][1], al[0][2], al[0][3], aLoB + aoff0 + kadd);
            ldsm4(al[1][0], al[1][1], al[1][2], al[1][3], aLoB + aoff1 + kadd);
            #pragma unroll
            for (int mi = 0; mi < 2; mi++)
                #pragma unroll
                for (int ni = 0; ni < 4; ni++)
                    mma_f16(acc[mi][ni], ah[mi], &bh[ni >> 1][(ni & 1) * 2]);
            #pragma unroll
            for (int mi = 0; mi < 2; mi++)
                #pragma unroll
                for (int ni = 0; ni < 4; ni++)
                    mma_f16(acc[mi][ni], ah[mi], &bl[ni >> 1][(ni & 1) * 2]);
            #pragma unroll
            for (int mi = 0; mi < 2; mi++)
                #pragma unroll
                for (int ni = 0; ni < 4; ni++)
                    mma_f16(acc[mi][ni], al[mi], &bh[ni >> 1][(ni & 1) * 2]);
        }
        __syncthreads();
    }

    #pragma unroll
    for (int mi = 0; mi < 2; mi++) {
        #pragma unroll
        for (int half = 0; half < 2; half++) {
            const int row = m0 + wm * 32 + mi * 16 + gid + half * 8;
            if (GUARD && row >= cq) continue;
            #pragma unroll
            for (int ni = 0; ni < 4; ni++) {
                const int col = n0 + wn * 32 + ni * 8 + tig * 2;
                if (EPI == 7) {
                    float* dst = C + (size_t)row * N + col;
                    atomicAdd(dst,     acc[mi][ni][half * 2 + 0] + bsc * bias[col]);
                    atomicAdd(dst + 1, acc[mi][ni][half * 2 + 1] + bsc * bias[col + 1]);
                    continue;
                }
                float vx = acc[mi][ni][half * 2 + 0] + bias[col];
                float vy = acc[mi][ni][half * 2 + 1] + bias[col + 1];
                if (EPI == 5) {
                    const float w = rw[row];
                    float* dst = C + (size_t)idx[row] * N + col;
                    atomicAdd(dst,     w * vx);
                    atomicAdd(dst + 1, w * vy);
                } else if (EPI == 6) {
                    vx = gelu1(vx); vy = gelu1(vy);
                    uint32_t hi, lo;
                    split2(vx, vy, hi, lo);
                    *(uint32_t*)&Ch[(size_t)row * N + col] = hi;
                    *(uint32_t*)&Cl[(size_t)row * N + col] = lo;
                } else {
                    *(float2*)(C + (size_t)row * N + col) = make_float2(vx, vy);
                }
            }
        }
    }
}

// ---------------------------------------------------------------------------
// fp32-input GEMM (front-end only). EPI: 0 store, 1 gelu, 2 res+v.
// ---------------------------------------------------------------------------
#define AH_SZ (64 * KST)
#define BH_SZ (128 * KST)
#define OFF_AH(b) ((b) * AH_SZ)
#define OFF_AL(b) (2 * AH_SZ + (b) * AH_SZ)
#define OFF_BH(b) (4 * AH_SZ + (b) * BH_SZ)
#define OFF_BL(b) (4 * AH_SZ + 2 * BH_SZ + (b) * BH_SZ)
#define SMEM_MMA ((4 * AH_SZ + 4 * BH_SZ) * 2)

template<int EPI>
__global__ void __launch_bounds__(256, 2) mma_gemm(
    const float* __restrict__ A, const float* __restrict__ B,
    const float* __restrict__ bias, float* __restrict__ C,
    int M, int N, int K, const float* __restrict__ res)
{
    const int t = threadIdx.x, wid = t >> 5, lane = t & 31;
    const int m0 = blockIdx.y * 64, n0 = blockIdx.x * 128;

    extern __shared__ __half sh[];
    const uint32_t sbase = (uint32_t)__cvta_generic_to_shared(sh);

    const int arow = t >> 2, akof = (t & 3) * 8;
    const float* Agp = A + (size_t)(m0 + arow) * K + akof;
    const int nB = t & 127, kk2 = t >> 7;
    const float* Bcol = B + n0 + nB;

    const int wm = wid >> 2, wn = wid & 3;
    const int gid = lane >> 2, tig = lane & 3;
    const int l7 = lane & 7, q8 = lane >> 3;
    const int A_row = (q8 & 1) * 8 + l7, A_k = (q8 >> 1) * 8;
    const int B_row = (q8 >> 1) * 8 + l7, B_k = (q8 & 1) * 8;
    const uint32_t aoff0 = (uint32_t)((wm * 32 + A_row) * KST + A_k) * 2u;
    const uint32_t aoff1 = aoff0 + 16u * KST * 2u;
    const uint32_t boff0 = (uint32_t)((wn * 32 + B_row) * KST + B_k) * 2u;
    const uint32_t boff1 = boff0 + 16u * KST * 2u;

    float4 pa0, pa1;
    float pb[16];

    pa0 = *(const float4*)(Agp);
    pa1 = *(const float4*)(Agp + 4);
    #pragma unroll
    for (int i = 0; i < 4; i++)
        #pragma unroll
        for (int jj = 0; jj < 4; jj++)
            pb[i * 4 + jj] = Bcol[(size_t)(kk2 * 16 + i * 4 + jj) * N];
    {
        uint32_t h0,l0,h1,l1,h2,l2,h3,l3;
        split2(pa0.x, pa0.y, h0, l0); split2(pa0.z, pa0.w, h1, l1);
        split2(pa1.x, pa1.y, h2, l2); split2(pa1.z, pa1.w, h3, l3);
        *(uint4*)&sh[OFF_AH(0) + arow * KST + akof] = make_uint4(h0,h1,h2,h3);
        *(uint4*)&sh[OFF_AL(0) + arow * KST + akof] = make_uint4(l0,l1,l2,l3);
        #pragma unroll
        for (int i = 0; i < 4; i++) {
            const int kb = kk2 * 16 + i * 4;
            uint32_t bh0,bl0,bh1,bl1;
            split2(pb[i*4+0], pb[i*4+1], bh0, bl0);
            split2(pb[i*4+2], pb[i*4+3], bh1, bl1);
            *(uint2*)&sh[OFF_BH(0) + nB * KST + kb] = make_uint2(bh0, bh1);
            *(uint2*)&sh[OFF_BL(0) + nB * KST + kb] = make_uint2(bl0, bl1);
        }
    }
    __syncthreads();

    float acc[2][4][4] = {};

    const int nkt = K >> 5;
    for (int j = 0; j < nkt; j++) {
        const int cur = j & 1;
        const bool more = (j + 1 < nkt);
        if (more) {
            const int k0 = (j + 1) << 5;
            pa0 = *(const float4*)(Agp + k0);
            pa1 = *(const float4*)(Agp + k0 + 4);
            #pragma unroll
            for (int i = 0; i < 4; i++)
                #pragma unroll
                for (int jj = 0; jj < 4; jj++)
                    pb[i * 4 + jj] = Bcol[(size_t)(k0 + kk2 * 16 + i * 4 + jj) * N];
        }
        {
            const uint32_t aHiB = sbase + (uint32_t)OFF_AH(cur) * 2u;
            const uint32_t aLoB = sbase + (uint32_t)OFF_AL(cur) * 2u;
            const uint32_t bHiB = sbase + (uint32_t)OFF_BH(cur) * 2u;
            const uint32_t bLoB = sbase + (uint32_t)OFF_BL(cur) * 2u;
            #pragma unroll
            for (int ks = 0; ks < 2; ks++) {
                const uint32_t kadd = (uint32_t)ks * 32u;
                uint32_t bh[2][4], bl[2][4], ah[2][4], al[2][4];
                ldsm4(bh[0][0], bh[0][1], bh[0][2], bh[0][3], bHiB + boff0 + kadd);
                ldsm4(bh[1][0], bh[1][1], bh[1][2], bh[1][3], bHiB + boff1 + kadd);
                ldsm4(bl[0][0], bl[0][1], bl[0][2], bl[0][3], bLoB + boff0 + kadd);
                ldsm4(bl[1][0], bl[1][1], bl[1][2], bl[1][3], bLoB + boff1 + kadd);
                ldsm4(ah[0][0], ah[0][1], ah[0][2], ah[0][3], aHiB + aoff0 + kadd);
                ldsm4(ah[1][0], ah[1][1], ah[1][2], ah[1][3], aHiB + aoff1 + kadd);
                ldsm4(al[0][0], al[0][1], al[0][2], al[0][3], aLoB + aoff0 + kadd);
                ldsm4(al[1][0], al[1][1], al[1][2], al[1][3], aLoB + aoff1 + kadd);
                #pragma unroll
                for (int mi = 0; mi < 2; mi++)
                    #pragma unroll
                    for (int ni = 0; ni < 4; ni++)
                        mma_f16(acc[mi][ni], ah[mi], &bh[ni >> 1][(ni & 1) * 2]);
                #pragma unroll
                for (int mi = 0; mi < 2; mi++)
                    #pragma unroll
                    for (int ni = 0; ni < 4; ni++)
                        mma_f16(acc[mi][ni], ah[mi], &bl[ni >> 1][(ni & 1) * 2]);
                #pragma unroll
                for (int mi = 0; mi < 2; mi++)
                    #pragma unroll
                    for (int ni = 0; ni < 4; ni++)
                        mma_f16(acc[mi][ni], al[mi], &bh[ni >> 1][(ni & 1) * 2]);
            }
        }
        if (more) {
            const int nxt = cur ^ 1;
            uint32_t h0,l0,h1,l1,h2,l2,h3,l3;
            split2(pa0.x, pa0.y, h0, l0); split2(pa0.z, pa0.w, h1, l1);
            split2(pa1.x, pa1.y, h2, l2); split2(pa1.z, pa1.w, h3, l3);
            *(uint4*)&sh[OFF_AH(nxt) + arow * KST + akof] = make_uint4(h0,h1,h2,h3);
            *(uint4*)&sh[OFF_AL(nxt) + arow * KST + akof] = make_uint4(l0,l1,l2,l3);
            #pragma unroll
            for (int i = 0; i < 4; i++) {
                const int kb = kk2 * 16 + i * 4;
                uint32_t bh0,bl0,bh1,bl1;
                split2(pb[i*4+0], pb[i*4+1], bh0, bl0);
                split2(pb[i*4+2], pb[i*4+3], bh1, bl1);
                *(uint2*)&sh[OFF_BH(nxt) + nB * KST + kb] = make_uint2(bh0, bh1);
                *(uint2*)&sh[OFF_BL(nxt) + nB * KST + kb] = make_uint2(bl0, bl1);
            }
            __syncthreads();
        }
    }

    #pragma unroll
    for (int mi = 0; mi < 2; mi++) {
        #pragma unroll
        for (int half = 0; half < 2; half++) {
            const int row = m0 + wm * 32 + mi * 16 + gid + half * 8;
            #pragma unroll
            for (int ni = 0; ni < 4; ni++) {
                const int col = n0 + wn * 32 + ni * 8 + tig * 2;
                float vx = acc[mi][ni][half * 2 + 0] + bias[col];
                float vy = acc[mi][ni][half * 2 + 1] + bias[col + 1];
                float* dst = C + (size_t)row * N + col;
                if (EPI == 1) {
                    vx = gelu1(vx); vy = gelu1(vy);
                } else if (EPI == 2) {
                    const float2 rr = *(const float2*)(res + (size_t)row * N + col);
                    vx += rr.x; vy += rr.y;
                }
                *(float2*)dst = make_float2(vx, vy);
            }
        }
    }
}

// ---------------------------------------------------------------------------
// Flash attention: block per (b,head), thread per query row; writes HALVES.
// ---------------------------------------------------------------------------
#define KVP 68
#define SMEM_ATTN (2 * 128 * KVP * 4)

__global__ void __launch_bounds__(128) attn_flash(const float* __restrict__ qkv,
                                                  __half* __restrict__ oh,
                                                  __half* __restrict__ ol)
{
    const int bh = blockIdx.x;
    const int b = bh >> 3, hh = bh & 7;
    const int t = threadIdx.x;
    const float* base = qkv + (size_t)b * 128 * 1536 + hh * 64;

    extern __shared__ float kv[];
    float (*Ks)[KVP] = (float(*)[KVP])kv;
    float (*Vs)[KVP] = (float(*)[KVP])(kv + 128 * KVP);

    {
        const float* kr = base + (size_t)t * 1536 + 512;
        const float* vr = kr + 512;
        #pragma unroll
        for (int d4 = 0; d4 < 16; d4++) {
            *(float4*)&Ks[t][d4 * 4] = *(const float4*)(kr + d4 * 4);
            *(float4*)&Vs[t][d4 * 4] = *(const float4*)(vr + d4 * 4);
        }
    }
    float q[64];
    {
        const float* qr = base + (size_t)t * 1536;
        #pragma unroll
        for (int d4 = 0; d4 < 16; d4++) {
            float4 f = *(const float4*)(qr + d4 * 4);
            q[d4 * 4 + 0] = f.x; q[d4 * 4 + 1] = f.y;
            q[d4 * 4 + 2] = f.z; q[d4 * 4 + 3] = f.w;
        }
    }
    __syncthreads();

    float oacc[64];
    #pragma unroll
    for (int d = 0; d < 64; d++) oacc[d] = 0.f;
    float m = -1e30f, l = 0.f;

    for (int j = 0; j <= t; j++) {
        float s = 0.f;
        #pragma unroll
        for (int d4 = 0; d4 < 16; d4++) {
            float4 k4 = *(const float4*)&Ks[j][d4 * 4];
            s += q[d4 * 4 + 0] * k4.x + q[d4 * 4 + 1] * k4.y
               + q[d4 * 4 + 2] * k4.z + q[d4 * 4 + 3] * k4.w;
        }
        s *= 0.125f;
        const float nm = fmaxf(m, s);
        const float sc = __expf(m - nm), e = __expf(s - nm);
        l = l * sc + e;
        m = nm;
        #pragma unroll
        for (int d4 = 0; d4 < 16; d4++) {
            float4 v4 = *(const float4*)&Vs[j][d4 * 4];
            oacc[d4 * 4 + 0] = oacc[d4 * 4 + 0] * sc + e * v4.x;
            oacc[d4 * 4 + 1] = oacc[d4 * 4 + 1] * sc + e * v4.y;
            oacc[d4 * 4 + 2] = oacc[d4 * 4 + 2] * sc + e * v4.z;
            oacc[d4 * 4 + 3] = oacc[d4 * 4 + 3] * sc + e * v4.w;
        }
    }
    const float inv = 1.0f / l;
    const size_t oo = ((size_t)b * 128 + t) * 512 + hh * 64;
    #pragma unroll
    for (int d4 = 0; d4 < 16; d4++) {
        uint32_t h0, l0, h1, l1;
        split2(oacc[d4 * 4 + 0] * inv, oacc[d4 * 4 + 1] * inv, h0, l0);
        split2(oacc[d4 * 4 + 2] * inv, oacc[d4 * 4 + 3] * inv, h1, l1);
        *(uint2*)&oh[oo + d4 * 4] = make_uint2(h0, h1);
        *(uint2*)&ol[oo + d4 * 4] = make_uint2(l0, l1);
    }
}

// ---------------------------------------------------------------------------
__global__ void patchnorm_kernel(const float* __restrict__ x, float* __restrict__ y)
{
    const int warp = threadIdx.x >> 5, lane = threadIdx.x & 31;
    const int row = blockIdx.x * 8 + warp;
    const float* xr = x + (size_t)row * 128;
    float4 f = *(const float4*)(xr + lane * 4);
    float s = f.x + f.y + f.z + f.w;
    #pragma unroll
    for (int o = 16; o; o >>= 1) s += __shfl_xor_sync(0xffffffffu, s, o);
    const float mu = s * (1.0f / 128.0f);
    float q = (f.x - mu) * (f.x - mu) + (f.y - mu) * (f.y - mu)
            + (f.z - mu) * (f.z - mu) + (f.w - mu) * (f.w - mu);
    #pragma unroll
    for (int o = 16; o; o >>= 1) q += __shfl_xor_sync(0xffffffffu, q, o);
    const float rs = rsqrtf(q * (1.0f / 128.0f) + 1e-6f);
    float4 r = make_float4((f.x - mu) * rs, (f.y - mu) * rs, (f.z - mu) * rs, (f.w - mu) * rs);
    *(float4*)(y + (size_t)row * 128 + lane * 4) = r;
}

// LN -> half hi/lo only. GATE: also softmax gate + top-2 routing.
// ZEROCNT: block 0 zeroes the routing counters (safe: runs before gate LN).
template<bool GATE, bool ZEROCNT>
__global__ void ln512g_kernel(const float* __restrict__ x,
                              __half* __restrict__ yh, __half* __restrict__ yl,
                              const float* __restrict__ g, const float* __restrict__ b,
                              const float* __restrict__ gw, const float* __restrict__ gb,
                              int* __restrict__ cnt, int* __restrict__ idx,
                              float* __restrict__ rw)
{
    if (ZEROCNT) {
        if (blockIdx.x == 0 && threadIdx.x < 4) cnt[threadIdx.x] = 0;
    }
    const int warp = threadIdx.x >> 5, lane = threadIdx.x & 31;
    const int row = blockIdx.x * 8 + warp;
    const float* xr = x + (size_t)row * 512;
    float v[16];
    float s = 0.f;
    #pragma unroll
    for (int c = 0; c < 4; c++) {
        float4 f = *(const float4*)(xr + c * 128 + lane * 4);
        v[c * 4 + 0] = f.x; v[c * 4 + 1] = f.y; v[c * 4 + 2] = f.z; v[c * 4 + 3] = f.w;
        s += f.x + f.y + f.z + f.w;
    }
    #pragma unroll
    for (int o = 16; o; o >>= 1) s += __shfl_xor_sync(0xffffffffu, s, o);
    const float mu = s * (1.0f / 512.0f);
    float q = 0.f;
    #pragma unroll
    for (int k = 0; k < 16; k++) { float d = v[k] - mu; q += d * d; }
    #pragma unroll
    for (int o = 16; o; o >>= 1) q += __shfl_xor_sync(0xffffffffu, q, o);
    const float rs = rsqrtf(q * (1.0f / 512.0f) + 1e-5f);
    #pragma unroll
    for (int c = 0; c < 4; c++) {
        const int col = c * 128 + lane * 4;
        float4 gg = *(const float4*)(g + col);
        float4 bb = *(const float4*)(b + col);
        float4 r;
        r.x = gg.x * (v[c * 4 + 0] - mu) * rs + bb.x;
        r.y = gg.y * (v[c * 4 + 1] - mu) * rs + bb.y;
        r.z = gg.z * (v[c * 4 + 2] - mu) * rs + bb.z;
        r.w = gg.w * (v[c * 4 + 3] - mu) * rs + bb.w;
        v[c * 4 + 0] = r.x; v[c * 4 + 1] = r.y;
        v[c * 4 + 2] = r.z; v[c * 4 + 3] = r.w;
        uint32_t h0, l0, h1, l1;
        split2(r.x, r.y, h0, l0);
        split2(r.z, r.w, h1, l1);
        *(uint2*)&yh[(size_t)row * 512 + col] = make_uint2(h0, h1);
        *(uint2*)&yl[(size_t)row * 512 + col] = make_uint2(l0, l1);
    }
    if (GATE) {
        float a0 = 0.f, a1 = 0.f, a2 = 0.f, a3 = 0.f;
        #pragma unroll
        for (int c = 0; c < 4; c++)
            #pragma unroll
            for (int j = 0; j < 4; j++) {
                const int col = c * 128 + lane * 4 + j;
                const float hv = v[c * 4 + j];
                float4 w = *(const float4*)(gw + (size_t)col * 4);
                a0 += hv * w.x; a1 += hv * w.y; a2 += hv * w.z; a3 += hv * w.w;
            }
        #pragma unroll
        for (int o = 16; o; o >>= 1) {
            a0 += __shfl_xor_sync(0xffffffffu, a0, o);
            a1 += __shfl_xor_sync(0xffffffffu, a1, o);
            a2 += __shfl_xor_sync(0xffffffffu, a2, o);
            a3 += __shfl_xor_sync(0xffffffffu, a3, o);
        }
        if (lane == 0) {
            float p[4] = {a0 + gb[0], a1 + gb[1], a2 + gb[2], a3 + gb[3]};
            const float mx = fmaxf(fmaxf(p[0], p[1]), fmaxf(p[2], p[3]));
            float ss = 0.f;
            #pragma unroll
            for (int e = 0; e < 4; e++) { p[e] = expf(p[e] - mx); ss += p[e]; }
            const float invs = 1.0f / ss;
            #pragma unroll
            for (int e = 0; e < 4; e++) p[e] *= invs;
            int i0 = 0;
            #pragma unroll
            for (int e = 1; e < 4; e++) if (p[e] > p[i0]) i0 = e;
            int i1 = -1;
            #pragma unroll
            for (int e = 0; e < 4; e++) if (e != i0 && (i1 < 0 || p[e] > p[i1])) i1 = e;
            int s0 = atomicAdd(&cnt[i0], 1);
            idx[i0 * T_TOK + s0] = row; rw[i0 * T_TOK + s0] = p[i0];
            int s1 = atomicAdd(&cnt[i1], 1);
            idx[i1 * T_TOK + s1] = row; rw[i1 * T_TOK + s1] = p[i1];
        }
    }
}

__global__ void freqadd_kernel(float* __restrict__ h, const float* __restrict__ emb,
                               const int* __restrict__ fid)
{
    const int i = blockIdx.x * 256 + threadIdx.x;
    const int row = i >> 9, d = i & 511, b = row >> 7;
    h[i] += emb[(size_t)fid[b] * 512 + d];
}

__global__ void head_kernel(const float* __restrict__ h,
                            const float* __restrict__ fng, const float* __restrict__ fnb,
                            const float* __restrict__ hg,  const float* __restrict__ hb,
                            const float* __restrict__ hw,  const float* __restrict__ hbias,
                            float* __restrict__ out, int out_size)
{
    const int warp = threadIdx.x >> 5, lane = threadIdx.x & 31;
    const int b = warp;
    const float* xr = h + ((size_t)b * 128 + 127) * 512;
    float v[16];
    float s = 0.f;
    #pragma unroll
    for (int c = 0; c < 4; c++) {
        float4 f = *(const float4*)(xr + c * 128 + lane * 4);
        v[c * 4 + 0] = f.x; v[c * 4 + 1] = f.y; v[c * 4 + 2] = f.z; v[c * 4 + 3] = f.w;
        s += f.x + f.y + f.z + f.w;
    }
    #pragma unroll
    for (int o = 16; o; o >>= 1) s += __shfl_xor_sync(0xffffffffu, s, o);
    float mu = s * (1.0f / 512.0f);
    float q = 0.f;
    #pragma unroll
    for (int k = 0; k < 16; k++) { float d = v[k] - mu; q += d * d; }
    #pragma unroll
    for (int o = 16; o; o >>= 1) q += __shfl_xor_sync(0xffffffffu, q, o);
    float rs = rsqrtf(q * (1.0f / 512.0f) + 1e-5f);
    #pragma unroll
    for (int c = 0; c < 4; c++)
        #pragma unroll
        for (int j = 0; j < 4; j++) {
            const int col = c * 128 + lane * 4 + j;
            v[c * 4 + j] = fng[col] * (v[c * 4 + j] - mu) * rs + fnb[col];
        }
    s = 0.f;
    #pragma unroll
    for (int k = 0; k < 16; k++) s += v[k];
    #pragma unroll
    for (int o = 16; o; o >>= 1) s += __shfl_xor_sync(0xffffffffu, s, o);
    mu = s * (1.0f / 512.0f);
    q = 0.f;
    #pragma unroll
    for (int k = 0; k < 16; k++) { float d = v[k] - mu; q += d * d; }
    #pragma unroll
    for (int o = 16; o; o >>= 1) q += __shfl_xor_sync(0xffffffffu, q, o);
    rs = rsqrtf(q * (1.0f / 512.0f) + 1e-5f);
    float dot = 0.f;
    #pragma unroll
    for (int c = 0; c < 4; c++)
        #pragma unroll
        for (int j = 0; j < 4; j++) {
            const int col = c * 128 + lane * 4 + j;
            const float hl = hg[col] * (v[c * 4 + j] - mu) * rs + hb[col];
            dot += hl * hw[col];
        }
    #pragma unroll
    for (int o = 16; o; o >>= 1) dot += __shfl_xor_sync(0xffffffffu, dot, o);
    if (lane == 0) {
        const float logit = dot + hbias[0];
        if (out_size >= 32) {
            out[b] = logit;
            out[16 + b] = 1.0f / (1.0f + expf(-logit));
        } else {
            out[b] = logit;
        }
    }
}

// ---------------------------------------------------------------------------
extern "C" void kernel_launch(void* const* d_in, const int* in_sizes, int n_in,
                              void* d_out, int out_size)
{
    const float* x        = (const float*)d_in[0];
    const int*   fid      = (const int*)  d_in[1];
    const float* ir_w1    = (const float*)d_in[2];
    const float* ir_b1    = (const float*)d_in[3];
    const float* ir_w2    = (const float*)d_in[4];
    const float* ir_b2    = (const float*)d_in[5];
    const float* p2m_w    = (const float*)d_in[6];
    const float* p2m_b    = (const float*)d_in[7];
    const float* freq_emb = (const float*)d_in[8];
    const float* ln1_g    = (const float*)d_in[9];
    const float* ln1_b    = (const float*)d_in[10];
    const float* qkv_w    = (const float*)d_in[11];
    const float* qkv_b    = (const float*)d_in[12];
    const float* out_w    = (const float*)d_in[13];
    const float* out_b    = (const float*)d_in[14];
    const float* ln2_g    = (const float*)d_in[15];
    const float* ln2_b    = (const float*)d_in[16];
    const float* gate_w   = (const float*)d_in[17];
    const float* gate_b   = (const float*)d_in[18];
    const float* exp_w1   = (const float*)d_in[19];
    const float* exp_b1   = (const float*)d_in[20];
    const float* exp_w2   = (const float*)d_in[21];
    const float* exp_b2   = (const float*)d_in[22];
    const float* fn_g     = (const float*)d_in[23];
    const float* fn_b     = (const float*)d_in[24];
    const float* head_g   = (const float*)d_in[25];
    const float* head_b   = (const float*)d_in[26];
    const float* head_w   = (const float*)d_in[27];
    const float* head_bias= (const float*)d_in[28];

    float *patches, *tmp, *hp, *h, *qkv, *rw;
    int *cnt, *idx;
    __half *qkvTh, *qkvTl, *outTh, *outTl, *e1Th, *e1Tl, *e2Th, *e2Tl;
    __half *hnh, *hnl, *ath, *atl, *ehh, *ehl;
    cudaGetSymbolAddress((void**)&patches, g_patches);
    cudaGetSymbolAddress((void**)&tmp,     g_tmp);
    cudaGetSymbolAddress((void**)&hp,      g_hp);
    cudaGetSymbolAddress((void**)&h,       g_h);
    cudaGetSymbolAddress((void**)&qkv,     g_qkv);
    cudaGetSymbolAddress((void**)&cnt,     g_cnt);
    cudaGetSymbolAddress((void**)&idx,     g_idx);
    cudaGetSymbolAddress((void**)&rw,      g_rw);
    cudaGetSymbolAddress((void**)&qkvTh,   g_qkvTh);
    cudaGetSymbolAddress((void**)&qkvTl,   g_qkvTl);
    cudaGetSymbolAddress((void**)&outTh,   g_outTh);
    cudaGetSymbolAddress((void**)&outTl,   g_outTl);
    cudaGetSymbolAddress((void**)&e1Th,    g_e1Th);
    cudaGetSymbolAddress((void**)&e1Tl,    g_e1Tl);
    cudaGetSymbolAddress((void**)&e2Th,    g_e2Th);
    cudaGetSymbolAddress((void**)&e2Tl,    g_e2Tl);
    cudaGetSymbolAddress((void**)&hnh,     g_hnh);
    cudaGetSymbolAddress((void**)&hnl,     g_hnl);
    cudaGetSymbolAddress((void**)&ath,     g_ath);
    cudaGetSymbolAddress((void**)&atl,     g_atl);
    cudaGetSymbolAddress((void**)&ehh,     g_ehh);
    cudaGetSymbolAddress((void**)&ehl,     g_ehl);

    cudaFuncSetAttribute(mma_gemm<0>, cudaFuncAttributeMaxDynamicSharedMemorySize, SMEM_MMA);
    cudaFuncSetAttribute(mma_gemm<1>, cudaFuncAttributeMaxDynamicSharedMemorySize, SMEM_MMA);
    cudaFuncSetAttribute(mma_gemm<2>, cudaFuncAttributeMaxDynamicSharedMemorySize, SMEM_MMA);
    cudaFuncSetAttribute(hgemm<0,false,false,false,1>, cudaFuncAttributeMaxDynamicSharedMemorySize, SMEM_HG);
    cudaFuncSetAttribute(hgemm<7,false,false,false,4>, cudaFuncAttributeMaxDynamicSharedMemorySize, SMEM_HG);
    cudaFuncSetAttribute(hgemm<6,true,true,true,1>,    cudaFuncAttributeMaxDynamicSharedMemorySize, SMEM_HG);
    cudaFuncSetAttribute(hgemm<5,false,true,true,1>,   cudaFuncAttributeMaxDynamicSharedMemorySize, SMEM_HG);
    cudaFuncSetAttribute(attn_flash, cudaFuncAttributeMaxDynamicSharedMemorySize, SMEM_ATTN);

    // ---- pre-split all weights ----
    wsplitT<<<dim3(24, 16, 12), 256>>>(qkv_w,  qkvTh, qkvTl, 512, 1536);
    wsplitT<<<dim3(8,  16, 12), 256>>>(out_w,  outTh, outTl, 512, 512);
    wsplitT<<<dim3(32, 16, 48), 256>>>(exp_w1, e1Th,  e1Tl,  512, 2048);
    wsplitT<<<dim3(8,  64, 48), 256>>>(exp_w2, e2Th,  e2Tl,  2048, 512);

    // ---- front end (fp32 path) ----
    patchnorm_kernel<<<256, 256>>>(x, patches);
    mma_gemm<1><<<dim3(4, 32), 256, SMEM_MMA>>>(patches, ir_w1, ir_b1, tmp,
        T_TOK, 512, 128, nullptr);
    mma_gemm<2><<<dim3(1, 32), 256, SMEM_MMA>>>(tmp, ir_w2, ir_b2, hp,
        T_TOK, 128, 512, patches);
    mma_gemm<0><<<dim3(4, 32), 256, SMEM_MMA>>>(hp, p2m_w, p2m_b, h,
        T_TOK, 512, 128, nullptr);
    freqadd_kernel<<<(T_TOK * 512) / 256, 256>>>(h, freq_emb, fid);

    const size_t EHZ = (size_t)T_TOK * HDIM;

    for (int l = 0; l < 12; l++) {
        // attention (LN also zeroes routing counters for this layer)
        ln512g_kernel<false, true><<<256, 256>>>(h, hnh, hnl,
            ln1_g + (size_t)l * 512, ln1_b + (size_t)l * 512,
            nullptr, nullptr, cnt, nullptr, nullptr);
        hgemm<0,false,false,false,1><<<dim3(12, 32), 256, SMEM_HG>>>(
            hnh, hnl, qkvTh + (size_t)l * 1536 * 512, qkvTl + (size_t)l * 1536 * 512,
            qkv_b + (size_t)l * 1536, qkv, nullptr, nullptr,
            T_TOK, 1536, 512, nullptr, nullptr, nullptr, 0, 0);
        attn_flash<<<128, 128, SMEM_ATTN>>>(qkv, ath, atl);
        hgemm<7,false,false,false,4><<<dim3(4, 32, 4), 256, SMEM_HG>>>(
            ath, atl, outTh + (size_t)l * 512 * 512, outTl + (size_t)l * 512 * 512,
            out_b + (size_t)l * 512, h, nullptr, nullptr,
            T_TOK, 512, 512, nullptr, nullptr, nullptr, 0, 0);
        // sparse MoE: LN + gate + routing fused
        ln512g_kernel<true, false><<<256, 256>>>(h, hnh, hnl,
            ln2_g + (size_t)l * 512, ln2_b + (size_t)l * 512,
            gate_w + (size_t)l * 512 * 4, gate_b + (size_t)l * 4, cnt, idx, rw);
        hgemm<6,true,true,true,1><<<dim3(16, 32, 4), 256, SMEM_HG>>>(
            hnh, hnl, e1Th + (size_t)l * 4 * 2048 * 512, e1Tl + (size_t)l * 4 * 2048 * 512,
            exp_b1 + (size_t)l * 4 * 2048, nullptr, ehh, ehl,
            T_TOK, 2048, 512, idx, nullptr, cnt, 0, EHZ);
        hgemm<5,false,true,true,1><<<dim3(4, 32, 4), 256, SMEM_HG>>>(
            ehh, ehl, e2Th + (size_t)l * 4 * 512 * 2048, e2Tl + (size_t)l * 4 * 512 * 2048,
            exp_b2 + (size_t)l * 4 * 512, h, nullptr, nullptr,
            T_TOK, 512, 2048, idx, rw, cnt, EHZ, 0);
    }

    head_kernel<<<1, 512>>>(h, fn_g, fn_b, head_g, head_b, head_w, head_bias,
                            (float*)d_out, out_size);
}